// round 3
// baseline (speedup 1.0000x reference)
#include <cuda_runtime.h>
#include <cuda_bf16.h>

#define T_STEPS 32768
#define NSTEP   (T_STEPS - 1)    // 32767 RK4 steps
#define BATCH   32
#define NS      18
#define NH      16
#define REC     36               // per-step record: w[18] + c[16] + pad
#define L2E     1.4426950408889634

// ---------------- device scratch (static, no allocation) ----------------
__device__ float g_Phi[NS * NS];      // state transition (exact RK4 collapse)
__device__ float g_M[NS];             // act coefficient vector
__device__ float g_PhiM[NS];          // Phi @ M  (pipelining constant)
__device__ float g_P1[NS], g_Pm[NS], g_Pn[NS];
__device__ float g_W1s[NH * NS];      // (2*L2E/STD) * W1[:, :18]
__device__ float g_W1Ms[NH];          // (2*L2E) * (W1'/STD) @ M
__device__ float g_cbs[NH], g_wtow[NH], g_wtod[NH];   // prescaled policy consts
__device__ float g_w2f[NH];           // w2 * 2^20 (fixed-point reduce)
__device__ float g_qb;                // -L2E * b2
__device__ float g_rec[NSTEP * REC + 256];

// ---------------- kernel 0: build step-invariant constants (fp64) -------
__global__ void k_setup(const float* __restrict__ W_A, const float* __restrict__ W_B,
                        const float* __restrict__ W1, const float* __restrict__ b1,
                        const float* __restrict__ w2, const float* __restrict__ b2)
{
    __shared__ double Ad[NS][NS], P2[NS][NS], P3[NS][NS];
    __shared__ double vr[NS], vt[NS], Md[NS];
    int i = threadIdx.x;
    double phid[NS];

    if (i < NS) {
        for (int j = 0; j < NS; j++)
            Ad[i][j] = 1e-4 * (double)W_A[i * NS + j] - (i == j ? 1e-3 : 0.0);
        double bt = 1e-6 * (double)W_B[i * 17 + 0];
        double br = 0.0;
        for (int c = 1; c < 17; c++) br += (double)W_B[i * 17 + c];
        vr[i] = br * (-16914.0 * 1e-6);
        vt[i] = bt;
    }
    __syncthreads();
    if (i < NS) {                         // A^2
        for (int j = 0; j < NS; j++) {
            double s = 0.0;
            for (int k = 0; k < NS; k++) s += Ad[i][k] * Ad[k][j];
            P2[i][j] = s;
        }
    }
    __syncthreads();
    if (i < NS) {                         // A^3
        for (int j = 0; j < NS; j++) {
            double s = 0.0;
            for (int k = 0; k < NS; k++) s += P2[i][k] * Ad[k][j];
            P3[i][j] = s;
        }
    }
    __syncthreads();
    if (i < NS) {
        // Phi = I + 30A + 450A^2 + 4500A^3 + 33750A^4
        for (int j = 0; j < NS; j++) {
            double a4 = 0.0;
            for (int k = 0; k < NS; k++) a4 += P3[i][k] * Ad[k][j];
            double phi = (i == j ? 1.0 : 0.0) + 30.0 * Ad[i][j] + 450.0 * P2[i][j]
                       + 4500.0 * P3[i][j] + 33750.0 * a4;
            phid[j] = phi;
            g_Phi[i * NS + j] = (float)phi;
        }
        double r1 = 0, r2 = 0, r3 = 0, u1 = 0, u2 = 0, u3 = 0;
        for (int k = 0; k < NS; k++) { r1 += Ad[i][k] * vr[k]; u1 += Ad[i][k] * vt[k]; }
        for (int k = 0; k < NS; k++) { r2 += P2[i][k] * vr[k]; u2 += P2[i][k] * vt[k]; }
        for (int k = 0; k < NS; k++) { r3 += P3[i][k] * vr[k]; u3 += P3[i][k] * vt[k]; }
        double M = 30.0 * vr[i] + 450.0 * r1 + 4500.0 * r2 + 33750.0 * r3;
        Md[i]   = M;
        g_M[i]  = (float)M;
        g_P1[i] = (float)( 5.0 * vt[i] + 150.0 * u1 + 2250.0 * u2 + 33750.0 * u3);
        g_Pm[i] = (float)(20.0 * vt[i] + 300.0 * u1 + 2250.0 * u2);
        g_Pn[i] = (float)( 5.0 * vt[i]);
    }
    __syncthreads();
    if (i < NS) {                         // PhiM = Phi @ M
        double s = 0.0;
        for (int j = 0; j < NS; j++) s += phid[j] * Md[j];
        g_PhiM[i] = (float)s;
    }
    if (i < NH) {
        // W1' = W1[:, :18]/STD, prescaled by 2*L2E for single-MUFU exp2 tanh
        double wm = 0.0, srow = 0.0;
        for (int j = 0; j < NS; j++) {
            double w = (double)W1[i * 20 + j] / 1.41;
            g_W1s[i * NS + j] = (float)(2.0 * L2E * w);
            wm   += w * Md[j];
            srow += w;
        }
        g_W1Ms[i] = (float)(2.0 * L2E * wm);
        double cb = (double)b1[i] - 23.359 * srow;       // b1 - (MU/STD)*sum(W1row)
        g_cbs[i]  = (float)(2.0 * L2E * cb);
        g_wtow[i] = (float)(2.0 * L2E * (double)W1[i * 20 + 18]);
        g_wtod[i] = (float)(2.0 * L2E * (double)W1[i * 20 + 19]);
        g_w2f[i]  = w2[i] * 1048576.0f;                  // * 2^20
    }
    if (i == 0) g_qb = (float)(-L2E * (double)b2[0]);
}

// ---------------- kernel 1: per-step records (parallel over steps) ------
// rec[k][0:18]  = tau(t)*P1 + tau(mid)*Pm + tau(tn)*Pn
// rec[k][18:34] = prescaled policy pre-activation constant
__global__ void k_steps(const float* __restrict__ t_eval, const float* __restrict__ Tt)
{
    int step = blockIdx.x * (blockDim.x >> 5) + (threadIdx.x >> 5);
    int lane = threadIdx.x & 31;
    if (step >= NSTEP) return;

    float t    = t_eval[step];
    float tau1 = Tt[step];
    float taun = Tt[step + 1];
    float taum = 0.5f * (tau1 + taun);       // exact midpoint on the 30s grid
    float tod  = fmodf(t, 86400.0f) / 86400.0f;
    float tow  = fmodf(t + 259200.0f, 604800.0f) / 604800.0f;

    float* rec = g_rec + step * REC;
    if (lane < NS)
        rec[lane] = tau1 * g_P1[lane] + taum * g_Pm[lane] + taun * g_Pn[lane];
    if (lane < NH)
        rec[NS + lane] = g_cbs[lane] + g_wtow[lane] * tow + g_wtod[lane] * tod;
}

// ---------------- kernel 2: sequential scan, warp-per-batch -------------
#define MATVEC(src, uo, vo) do {                                              \
    float a0_ = 0.f, a1_ = 0.f, b0_ = 0.f, b1_ = 0.f;                         \
    _Pragma("unroll")                                                         \
    for (int j_ = 0; j_ < NS; j_++) {                                         \
        float xj_ = __shfl_sync(0xffffffffu, (src), j_);                      \
        if (j_ & 1) { a1_ = fmaf(Phi[j_], xj_, a1_); b1_ = fmaf(W1r[j_], xj_, b1_); } \
        else        { a0_ = fmaf(Phi[j_], xj_, a0_); b0_ = fmaf(W1r[j_], xj_, b0_); } \
    }                                                                         \
    (uo) = a0_ + a1_; (vo) = b0_ + b1_;                                       \
} while (0)

// act = sigmoid(w2 . tanh(zz-domain)) with both exps as single MUFU.EX2
#define POLICY(zz, actout) do {                                               \
    float e_, r_, q_, e2_, r2_;                                               \
    asm("ex2.approx.f32 %0, %1;" : "=f"(e_) : "f"(zz));                       \
    asm("rcp.approx.f32 %0, %1;" : "=f"(r_) : "f"(e_ + 1.0f));                \
    float h_ = fmaf(-2.0f, r_, 1.0f);          /* tanh */                     \
    int fi_ = __float2int_rn(h_ * w2fi);                                      \
    int S_  = __reduce_add_sync(0xffffffffu, fi_);   /* = 2*sum (halves dup) */\
    q_ = fmaf((float)S_, SCLQ, qb);                                           \
    asm("ex2.approx.f32 %0, %1;" : "=f"(e2_) : "f"(q_));                      \
    asm("rcp.approx.f32 %0, %1;" : "=f"(r2_) : "f"(e2_ + 1.0f));              \
    (actout) = r2_;                                                           \
} while (0)

#define STEP_BODY(wq, cq) do {                                                \
    float xk_ = fmaf(act, Mi, z);                  /* x_k */                  \
    if (lane < NS) op[lane] = xk_;                                            \
    op += BATCH * NS;                                                         \
    float zn_ = fmaf(act, PhiMi, u) + (wq);        /* z_k */                  \
    float zz_ = fmaf(act, wmsi, v + (cq));         /* policy preact */        \
    { int pk_ = (kpre < NSTEP) ? kpre : (NSTEP - 1);                          \
      (wq) = g_rec[pk_ * REC + si];                                           \
      (cq) = g_rec[pk_ * REC + NS + hi];                                      \
      kpre++; }                                                               \
    MATVEC(zn_, u, v);                             /* overlaps POLICY */      \
    POLICY(zz_, act);                                                         \
    z = zn_;                                                                  \
} while (0)

__global__ void __launch_bounds__(32, 1)
k_scan(const float* __restrict__ iv, float* __restrict__ out)
{
    const float SCLQ = -(float)(L2E / 2097152.0);  // -log2e * 2^-21 (dup halves)
    int b    = blockIdx.x;
    int lane = threadIdx.x;
    int si   = (lane < NS) ? lane : 0;
    int hi   = lane & (NH - 1);                    // lanes 16..31 duplicate hidden

    float Phi[NS], W1r[NS];
#pragma unroll
    for (int j = 0; j < NS; j++) {
        Phi[j] = (lane < NS) ? g_Phi[lane * NS + j] : 0.0f;
        W1r[j] = g_W1s[hi * NS + j];
    }
    float Mi    = (lane < NS) ? g_M[lane]    : 0.0f;
    float PhiMi = (lane < NS) ? g_PhiM[lane] : 0.0f;
    float wmsi  = g_W1Ms[hi];
    float w2fi  = g_w2f[hi];
    float qb    = g_qb;

    // ---- prologue: x_0, act_0, z_0 ----
    float x = (lane < NS) ? iv[b * NS + lane] : 0.0f;
    if (lane < NS) out[b * NS + lane] = x;         // row 0 = iv

    float u, v, act, z;
    MATVEC(x, u, v);                               // u = Phi x0, v = W1' x0
    {
        float cs0 = g_rec[NS + hi];
        float w0  = g_rec[si];
        float zz0 = v + cs0;
        POLICY(zz0, act);                          // act_0
        z = u + w0;                                // z_0
    }
    MATVEC(z, u, v);                               // matvecs of z_0

    // prefetch queue: records k = 1, 2, 3
    int kpre = 1;
    float wq0 = g_rec[1 * REC + si], cq0 = g_rec[1 * REC + NS + hi];
    float wq1 = g_rec[2 * REC + si], cq1 = g_rec[2 * REC + NS + hi];
    float wq2 = g_rec[3 * REC + si], cq2 = g_rec[3 * REC + NS + hi];
    kpre = 4;

    float* op = out + BATCH * NS + b * NS;         // row 1

    // ---- main loop: k = 1 .. 32766, 32766 = 3 * 10922 ----
    for (int g = 0; g < (NSTEP - 1) / 3; g++) {
        STEP_BODY(wq0, cq0);
        STEP_BODY(wq1, cq1);
        STEP_BODY(wq2, cq2);
    }

    // ---- epilogue: x_32767 ----
    float xl = fmaf(act, Mi, z);
    if (lane < NS) op[lane] = xl;
}

// ---------------- launch ------------------------------------------------
extern "C" void kernel_launch(void* const* d_in, const int* in_sizes, int n_in,
                              void* d_out, int out_size)
{
    const float* t_eval = (const float*)d_in[0];
    const float* iv     = (const float*)d_in[1];
    const float* W_A    = (const float*)d_in[2];
    const float* W_B    = (const float*)d_in[3];
    const float* W1     = (const float*)d_in[4];
    const float* b1     = (const float*)d_in[5];
    const float* w2     = (const float*)d_in[6];
    const float* b2     = (const float*)d_in[7];
    const float* Tt     = (const float*)d_in[8];
    float* out = (float*)d_out;

    k_setup<<<1, 32>>>(W_A, W_B, W1, b1, w2, b2);
    k_steps<<<(NSTEP + 7) / 8, 256>>>(t_eval, Tt);
    k_scan<<<BATCH, 32>>>(iv, out);
}

// round 8
// speedup vs baseline: 1.5307x; 1.5307x over previous
#include <cuda_runtime.h>
#include <cuda_bf16.h>

#define T_STEPS 32768
#define NSTEP   (T_STEPS - 1)    // 32767 RK4 steps; outputs x_1..x_32767
#define BATCH   32
#define NS      18
#define NH      16
typedef unsigned long long ull;

// ---------------- device scratch (static, no allocation) ----------------
__device__ float g_Phi[NS * NS];        // Phi (exact RK4 collapse), prologue
__device__ float g_G[NH * NS];          // W1[:, :18]/STD, prologue
__device__ float g_M[NS];               // act coefficient vector, prologue
__device__ float g_P1[NS], g_Pm[NS], g_Pn[NS];          // tau forcing basis
__device__ float g_PhP1[NS], g_PhPm[NS], g_PhPn[NS];    // Phi @ basis
__device__ float g_GP1[NH], g_GPm[NH], g_GPn[NH];       // G @ basis
__device__ float g_hA2[NS], g_hA1[NS], g_hM[NS];        // .5*Phi2M, .5*PhiM, .5*M
__device__ float g_hB2[NH], g_hB1[NH];                  // .5*GPhiM, .5*GM
__device__ float g_cb[NH], g_wtow[NH], g_wtod[NH];
__device__ float g_w2f[NH];             // w2 * 2^21 (fixed-point redux scaling)
__device__ float g_b2h;                 // b2/2
__device__ ull   g_PK[32 * NS];         // packed rows: lo=Phi2[lane], hi=GPhi[lane&15]
__device__ ull   g_rec2[NSTEP * 32 + 64];  // packed per-step record (W_k, C_k)

// ---------------- packed f32x2 / activation helpers ----------------------
#define FMA2(acc, a, b)  asm("fma.rn.f32x2 %0, %1, %2, %0;" : "+l"(acc) : "l"(a), "l"(b))
#define PACKDUP(d, s)    asm("mov.b64 %0, {%1, %1};" : "=l"(d) : "f"(s))
#define UNPACK2(lo, hi, v) asm("mov.b64 {%0, %1}, %2;" : "=f"(lo), "=f"(hi) : "l"(v))
#define ADD2(d, a, b)    asm("add.rn.f32x2 %0, %1, %2;" : "=l"(d) : "l"(a), "l"(b))
#define TANHA(d, s)      asm("tanh.approx.f32 %0, %1;" : "=f"(d) : "f"(s))

// th = tanh((w2 . tanh(s) + b2)/2);  act = 0.5 + 0.5*th (folded downstream)
// 16-lane dot via s32 REDUX (f32 redux unsupported on sm_103):
//   fi = rn(h * w2 * 2^21);  S = sum32 = 2 * sum16 = real * 2^22
//   a  = real/2 + b2/2 = S * 2^-23 + b2h
#define SCLQ 1.1920928955078125e-7f      /* 2^-23 */
#define POLICY2(th_out, s_in) do {                                            \
    float h_, a_;                                                             \
    TANHA(h_, (s_in));                                                        \
    int fi_ = __float2int_rn(h_ * w2f);                                       \
    int S_  = __reduce_add_sync(0xffffffffu, fi_);                            \
    a_ = fmaf((float)S_, SCLQ, b2h);                                          \
    TANHA((th_out), a_);                                                      \
} while (0)

// ---------------- kernel 0: constants, fp64, 576 threads -----------------
__global__ void k_setup(const float* __restrict__ W_A, const float* __restrict__ W_B,
                        const float* __restrict__ W1, const float* __restrict__ b1,
                        const float* __restrict__ w2, const float* __restrict__ b2)
{
    __shared__ double A[324], T1[324], T2[324], PH[324], PH2[324];
    __shared__ double G[288], GP[288];
    __shared__ double vt[NS], vr[NS], Md[NS], P1d[NS], Pmd[NS], Pnd[NS];
    int t = threadIdx.x;
    int i = t / NS, j = t % NS;

    if (t < 324) A[t] = 1e-4 * (double)W_A[t] - (i == j ? 1e-3 : 0.0);
    if (t < NS) {
        vt[t] = 1e-6 * (double)W_B[t * 17 + 0];
        double s = 0.0;
        for (int c = 1; c < 17; c++) s += (double)W_B[t * 17 + c];
        vr[t] = s * (-16914.0 * 1e-6);
    }
    if (t < 288) G[t] = (double)W1[(t / NS) * 20 + (t % NS)] / 1.41;
    __syncthreads();
    if (t < 324) {                              // A^2
        double s = 0.0;
        for (int k = 0; k < NS; k++) s += A[i * NS + k] * A[k * NS + j];
        T1[t] = s;
    }
    __syncthreads();
    if (t < 324) {                              // A^3
        double s = 0.0;
        for (int k = 0; k < NS; k++) s += T1[i * NS + k] * A[k * NS + j];
        T2[t] = s;
    }
    __syncthreads();
    if (t < 324) {                              // Phi = I+30A+450A^2+4500A^3+33750A^4
        double a4 = 0.0;
        for (int k = 0; k < NS; k++) a4 += T2[i * NS + k] * A[k * NS + j];
        double ph = (i == j ? 1.0 : 0.0) + 30.0 * A[t] + 450.0 * T1[t]
                  + 4500.0 * T2[t] + 33750.0 * a4;
        PH[t] = ph;
        g_Phi[t] = (float)ph;
    }
    if (t < NS) {                               // forcing basis + M
        double r1 = 0, r2 = 0, r3 = 0, u1 = 0, u2 = 0, u3 = 0;
        for (int k = 0; k < NS; k++) { r1 += A[t * NS + k] * vr[k];  u1 += A[t * NS + k] * vt[k]; }
        for (int k = 0; k < NS; k++) { r2 += T1[t * NS + k] * vr[k]; u2 += T1[t * NS + k] * vt[k]; }
        for (int k = 0; k < NS; k++) { r3 += T2[t * NS + k] * vr[k]; u3 += T2[t * NS + k] * vt[k]; }
        Md[t]  = 30.0 * vr[t] + 450.0 * r1 + 4500.0 * r2 + 33750.0 * r3;
        P1d[t] =  5.0 * vt[t] + 150.0 * u1 + 2250.0 * u2 + 33750.0 * u3;
        Pmd[t] = 20.0 * vt[t] + 300.0 * u1 + 2250.0 * u2;
        Pnd[t] =  5.0 * vt[t];
        g_M[t]  = (float)Md[t];
        g_P1[t] = (float)P1d[t]; g_Pm[t] = (float)Pmd[t]; g_Pn[t] = (float)Pnd[t];
    }
    __syncthreads();
    if (t < 324) {                              // Phi^2
        double s = 0.0;
        for (int k = 0; k < NS; k++) s += PH[i * NS + k] * PH[k * NS + j];
        PH2[t] = s;
    }
    if (t < 288) {                              // G @ Phi
        int m = t / NS, jj = t % NS;
        double s = 0.0;
        for (int k = 0; k < NS; k++) s += G[m * NS + k] * PH[k * NS + jj];
        GP[t] = s;
        g_G[t] = (float)G[t];
    }
    __syncthreads();
    if (t < NS) {
        double a2 = 0, a1 = 0, q1 = 0, qm = 0, qn = 0;
        for (int k = 0; k < NS; k++) {
            a2 += PH2[t * NS + k] * Md[k];
            a1 += PH[t * NS + k] * Md[k];
            q1 += PH[t * NS + k] * P1d[k];
            qm += PH[t * NS + k] * Pmd[k];
            qn += PH[t * NS + k] * Pnd[k];
        }
        g_hA2[t] = (float)(0.5 * a2);
        g_hA1[t] = (float)(0.5 * a1);
        g_hM[t]  = (float)(0.5 * Md[t]);
        g_PhP1[t] = (float)q1; g_PhPm[t] = (float)qm; g_PhPn[t] = (float)qn;
    }
    if (t < NH) {
        double b2v = 0, b1v = 0, e1 = 0, em = 0, en = 0, srow = 0;
        for (int k = 0; k < NS; k++) {
            b2v += GP[t * NS + k] * Md[k];
            b1v += G[t * NS + k]  * Md[k];
            e1  += G[t * NS + k]  * P1d[k];
            em  += G[t * NS + k]  * Pmd[k];
            en  += G[t * NS + k]  * Pnd[k];
            srow += G[t * NS + k];
        }
        g_hB2[t] = (float)(0.5 * b2v);
        g_hB1[t] = (float)(0.5 * b1v);
        g_GP1[t] = (float)e1; g_GPm[t] = (float)em; g_GPn[t] = (float)en;
        g_cb[t]   = (float)((double)b1[t] - 23.359 * srow);   // b1 - mu*sum(Grow)
        g_wtow[t] = W1[t * 20 + 18];
        g_wtod[t] = W1[t * 20 + 19];
        g_w2f[t]  = w2[t] * 2097152.0f;          // * 2^21
    }
    if (t == 0) g_b2h = 0.5f * b2[0];
    __syncthreads();
    if (t < 576) {                              // packed rows for the scan
        int lane = t / NS, jj = t % NS;
        float lo = (lane < NS) ? (float)PH2[lane * NS + jj] : 0.0f;
        float hf = (float)GP[(lane & (NH - 1)) * NS + jj];
        g_PK[lane * NS + jj] = ((ull)__float_as_uint(hf) << 32) | (ull)__float_as_uint(lo);
    }
}

// ---------------- kernel 1: per-step packed records ----------------------
// W_k = w_k + Phi*w_{k-1} + .5*Phi2M + .5*PhiM   (state const, low half)
// C_k = c_k + G*w_{k-1}   + .5*GPhiM + .5*GM     (policy const, high half)
__global__ void k_steps(const float* __restrict__ t_eval, const float* __restrict__ Tt)
{
    int step = blockIdx.x * (blockDim.x >> 5) + (threadIdx.x >> 5);
    int lane = threadIdx.x & 31;
    if (step >= NSTEP) return;

    float tau1 = Tt[step], taun = Tt[step + 1];
    float taum = 0.5f * (tau1 + taun);
    int   sm1  = (step > 0) ? (step - 1) : 0;
    float tp1  = Tt[sm1], tpn = Tt[sm1 + 1];
    float tpm  = 0.5f * (tp1 + tpn);
    float t    = t_eval[step];
    float tod  = fmodf(t, 86400.0f) * (1.0f / 86400.0f);
    float tow  = fmodf(t + 259200.0f, 604800.0f) * (1.0f / 604800.0f);

    float Wl = 0.0f;
    if (lane < NS)
        Wl = tau1 * g_P1[lane] + taum * g_Pm[lane] + taun * g_Pn[lane]
           + tp1 * g_PhP1[lane] + tpm * g_PhPm[lane] + tpn * g_PhPn[lane]
           + g_hA2[lane] + g_hA1[lane];
    int hi = lane & (NH - 1);
    float Cl = g_cb[hi] + g_wtow[hi] * tow + g_wtod[hi] * tod
             + tp1 * g_GP1[hi] + tpm * g_GPm[hi] + tpn * g_GPn[hi]
             + g_hB2[hi] + g_hB1[hi];

    g_rec2[step * 32 + lane] = ((ull)__float_as_uint(Cl) << 32) | (ull)__float_as_uint(Wl);
}

// ---------------- kernel 2: sequential scan, warp-per-batch --------------
__global__ void __launch_bounds__(32, 1)
k_scan(const float* __restrict__ iv, const float* __restrict__ t_eval,
       const float* __restrict__ Tt, float* __restrict__ out)
{
    __shared__ float2 sz[2][NS];
    int b = blockIdx.x, lane = threadIdx.x, hi = lane & (NH - 1);
    bool sl = (lane < NS);

    ull PK[NS];
#pragma unroll
    for (int j = 0; j < NS; j++) PK[j] = g_PK[lane * NS + j];
    float hA2 = sl ? g_hA2[lane] : 0.f, hA1 = sl ? g_hA1[lane] : 0.f;
    float hM  = sl ? g_hM[lane]  : 0.f, Ml  = sl ? g_M[lane]   : 0.f;
    float hB2 = g_hB2[hi], hB1 = g_hB1[hi];
    float w2f = g_w2f[hi], b2h = g_b2h;

    // prologue-only rows
    float Ph[NS], Gr[NS];
#pragma unroll
    for (int j = 0; j < NS; j++) {
        Ph[j] = sl ? g_Phi[lane * NS + j] : 0.f;
        Gr[j] = g_G[hi * NS + j];
    }
    float P1l = sl ? g_P1[lane] : 0.f, Pml = sl ? g_Pm[lane] : 0.f, Pnl = sl ? g_Pn[lane] : 0.f;
    float cbl = g_cb[hi], wtowl = g_wtow[hi], wtodl = g_wtod[hi];

    float x0 = sl ? iv[b * NS + lane] : 0.f;
    if (sl) out[b * NS + lane] = x0;                        // row 0 = iv

    // ---- step 0 (direct) ----
    float ta = Tt[0], tb = Tt[1], tm = 0.5f * (ta + tb);
    float w0 = ta * P1l + tm * Pml + tb * Pnl;
    float tv = t_eval[0];
    float tod = fmodf(tv, 86400.0f) * (1.0f / 86400.0f);
    float tow = fmodf(tv + 259200.0f, 604800.0f) * (1.0f / 604800.0f);
    float s0 = cbl + wtowl * tow + wtodl * tod, z0 = w0;
#pragma unroll
    for (int j = 0; j < NS; j++) {
        float xj = __shfl_sync(0xffffffffu, x0, j);
        s0 = fmaf(Gr[j], xj, s0);
        z0 = fmaf(Ph[j], xj, z0);
    }
    float th0; POLICY2(th0, s0);
    float a0 = fmaf(0.5f, th0, 0.5f);
    float x1 = fmaf(a0, Ml, z0);
    if (sl) out[1 * BATCH * NS + b * NS + lane] = x1;

    // ---- step 1 (direct) ----
    ta = Tt[1]; tb = Tt[2]; tm = 0.5f * (ta + tb);
    float w1 = ta * P1l + tm * Pml + tb * Pnl;
    tv = t_eval[1];
    tod = fmodf(tv, 86400.0f) * (1.0f / 86400.0f);
    tow = fmodf(tv + 259200.0f, 604800.0f) * (1.0f / 604800.0f);
    float s1 = cbl + wtowl * tow + wtodl * tod, z1 = w1;
#pragma unroll
    for (int j = 0; j < NS; j++) {
        float xj = __shfl_sync(0xffffffffu, x1, j);
        s1 = fmaf(Gr[j], xj, s1);
        z1 = fmaf(Ph[j], xj, z1);
    }
    float th1; POLICY2(th1, s1);
    float a1 = fmaf(0.5f, th1, 0.5f);
    float x2 = fmaf(a1, Ml, z1);
    if (sl) out[2 * BATCH * NS + b * NS + lane] = x2;

    // ---- seed packed matvecs of z0, z1 (shuffle path, once) ----
    ull accA = 0ull, accB = 0ull;
#pragma unroll
    for (int j = 0; j < NS; j++) {
        float zj = __shfl_sync(0xffffffffu, z0, j);
        ull zz; PACKDUP(zz, zj);
        FMA2(accA, PK[j], zz);
    }
#pragma unroll
    for (int j = 0; j < NS; j++) {
        float zj = __shfl_sync(0xffffffffu, z1, j);
        ull zz; PACKDUP(zz, zj);
        FMA2(accB, PK[j], zz);
    }

    float th2s = th0, th1s = th1;
    ull R0 = g_rec2[2 * 32 + lane], R1 = g_rec2[3 * 32 + lane];
    ull R2 = g_rec2[4 * 32 + lane], R3 = g_rec2[5 * 32 + lane];
    float* op = out + 3 * BATCH * NS + b * NS;

    // ---- steady loop: k = 2 .. 32766 ----
#pragma unroll 5
    for (int k = 2; k < NSTEP; k++) {
        float u, v;  UNPACK2(u, v, accA);       // Phi2*z_{k-2}, GPhi*z_{k-2}
        float Wk, Ck; UNPACK2(Wk, Ck, R0);

        float spre = fmaf(th2s, hB2, v + Ck);
        float s    = fmaf(th1s, hB1, spre);     // on chain: +1 fma
        float th;  POLICY2(th, s);              // tanh -> s32 redux -> tanh

        float zpre = fmaf(th2s, hA2, u + Wk);
        float z    = fmaf(th1s, hA1, zpre);
        float x    = fmaf(th, hM, z + hM);      // x_{k+1} = z + (0.5+0.5th)*M
        if (sl) op[lane] = x;
        op += BATCH * NS;

        int slot = k & 1;
        if (sl) sz[slot][lane] = make_float2(z, z);
        __syncwarp();
        ull acc0 = 0ull, acc1 = 0ull;
#pragma unroll
        for (int j = 0; j < NS; j++) {          // 18 LDS.64 broadcast + packed FMA
            ull zz = *(const ull*)&sz[slot][j];
            if (j & 1) { FMA2(acc1, PK[j], zz); }
            else       { FMA2(acc0, PK[j], zz); }
        }
        ull accN; ADD2(accN, acc0, acc1);

        accA = accB; accB = accN;
        th2s = th1s; th1s = th;
        R0 = R1; R1 = R2; R2 = R3;
        int kp = k + 4; kp = (kp > NSTEP - 1) ? (NSTEP - 1) : kp;
        R3 = g_rec2[kp * 32 + lane];
    }
}

// ---------------- launch ------------------------------------------------
extern "C" void kernel_launch(void* const* d_in, const int* in_sizes, int n_in,
                              void* d_out, int out_size)
{
    const float* t_eval = (const float*)d_in[0];
    const float* iv     = (const float*)d_in[1];
    const float* W_A    = (const float*)d_in[2];
    const float* W_B    = (const float*)d_in[3];
    const float* W1     = (const float*)d_in[4];
    const float* b1     = (const float*)d_in[5];
    const float* w2     = (const float*)d_in[6];
    const float* b2     = (const float*)d_in[7];
    const float* Tt     = (const float*)d_in[8];
    float* out = (float*)d_out;

    k_setup<<<1, 576>>>(W_A, W_B, W1, b1, w2, b2);
    k_steps<<<(NSTEP + 7) / 8, 256>>>(t_eval, Tt);
    k_scan<<<BATCH, 32>>>(iv, t_eval, Tt, out);
}

// round 9
// speedup vs baseline: 1.6275x; 1.0632x over previous
#include <cuda_runtime.h>
#include <cuda_bf16.h>

#define T_STEPS 32768
#define NSTEP   (T_STEPS - 1)    // 32767 RK4 steps; outputs x_1..x_32767
#define BATCH   32
#define NS      18
#define NH      16
typedef unsigned long long ull;

// ---------------- device scratch (static, no allocation) ----------------
__device__ float g_Phi[NS * NS];        // Phi (exact RK4 collapse), prologue
__device__ float g_G[NH * NS];          // W1[:, :18]/STD, prologue
__device__ float g_P1[NS], g_Pm[NS], g_Pn[NS];          // tau forcing basis
__device__ float g_PhP1[NS], g_PhPm[NS], g_PhPn[NS];    // Phi @ basis
__device__ float g_GP1[NH], g_GPm[NH], g_GPn[NH];       // G @ basis
__device__ float g_hA2[NS], g_hA1[NS], g_hM[NS];        // .5*Phi2M, .5*PhiM, .5*M
__device__ float g_hB2[NH], g_hB1[NH];                  // .5*GPhiM, .5*GM
__device__ float g_cb[NH], g_wtow[NH], g_wtod[NH];
__device__ float g_w2m[NH];             // w2 * SCL (adaptive fixed-point scale)
__device__ float g_sclv;                // 1/(4*SCL)
__device__ float g_cbr;                 // b2/2 - MAGICF/(4*SCL)
__device__ ull   g_PK[32 * NS];         // packed rows: lo=Phi2[lane], hi=GPhi[lane&15]
__device__ ull   g_rec2[(NSTEP + 8) * 32];  // packed per-step record (W_k, C_k)

// ---------------- packed f32x2 / activation helpers ----------------------
#define FMA2(acc, a, b)  asm("fma.rn.f32x2 %0, %1, %2, %0;" : "+l"(acc) : "l"(a), "l"(b))
#define PACKDUP(d, s)    asm("mov.b64 %0, {%1, %1};" : "=l"(d) : "f"(s))
#define PACK2(d, lo, hi) asm("mov.b64 %0, {%1, %2};" : "=l"(d) : "f"(lo), "f"(hi))
#define UNPACK2(lo, hi, v) asm("mov.b64 {%0, %1}, %2;" : "=f"(lo), "=f"(hi) : "l"(v))
#define ADD2(d, a, b)    asm("add.rn.f32x2 %0, %1, %2;" : "=l"(d) : "l"(a), "l"(b))
#define TANHA(d, s)      asm("tanh.approx.f32 %0, %1;" : "=f"(d) : "f"(s))

// ---- policy: th = tanh((w2 . tanh(s) + b2)/2) via magic-number fixed point
// fb = h*w2*SCL + 1.5*2^23  -> bits = MAGICI + round(h*w2*SCL)
// REDUX.u32 over 32 lanes (hidden units duplicated in both halves):
//   S' = 32*MAGICI + n  (mod 2^32),  n = 2*SCL*dot
// restore: af = uint_as_float(S' - 31*MAGICI) = MAGICF + n
// a = af/(4*SCL) + (b2/2 - MAGICF/(4*SCL)) = dot/2 + b2/2
#define MAGICF 12582912.0f
#define KADJ   (0u - 31u * 0x4B400000u)
#define POLICYM(th_out, s_in) do {                                            \
    float h_; TANHA(h_, (s_in));                                              \
    float fb_ = fmaf(h_, w2m, MAGICF);                                        \
    unsigned su_ = __reduce_add_sync(0xffffffffu, __float_as_uint(fb_));      \
    float af_ = __uint_as_float(su_ + KADJ);                                  \
    float a_ = fmaf(af_, sclv, cbr);                                          \
    TANHA((th_out), a_);                                                      \
} while (0)

// ---------------- kernel 0: constants, fp64, 576 threads -----------------
__global__ void k_setup(const float* __restrict__ W_A, const float* __restrict__ W_B,
                        const float* __restrict__ W1, const float* __restrict__ b1,
                        const float* __restrict__ w2, const float* __restrict__ b2)
{
    __shared__ double A[324], T1[324], T2[324], PH[324], PH2[324];
    __shared__ double G[288], GP[288];
    __shared__ double vt[NS], vr[NS], Md[NS], P1d[NS], Pmd[NS], Pnd[NS];
    __shared__ double s_scl;
    int t = threadIdx.x;
    int i = t / NS, j = t % NS;

    if (t < 324) A[t] = 1e-4 * (double)W_A[t] - (i == j ? 1e-3 : 0.0);
    if (t < NS) {
        vt[t] = 1e-6 * (double)W_B[t * 17 + 0];
        double s = 0.0;
        for (int c = 1; c < 17; c++) s += (double)W_B[t * 17 + c];
        vr[t] = s * (-16914.0 * 1e-6);
    }
    if (t < 288) G[t] = (double)W1[(t / NS) * 20 + (t % NS)] / 1.41;
    if (t == 0) {
        double ss = 0.0;
        for (int k = 0; k < NH; k++) ss += fabs((double)w2[k]);
        double SCL = exp2(floor(20.0 - log2(ss > 1.0 ? ss : 1.0)));
        s_scl  = SCL;
        g_sclv = (float)(1.0 / (4.0 * SCL));
        g_cbr  = (float)(0.5 * (double)b2[0] - (double)MAGICF / (4.0 * SCL));
    }
    __syncthreads();
    if (t < 324) {                              // A^2
        double s = 0.0;
        for (int k = 0; k < NS; k++) s += A[i * NS + k] * A[k * NS + j];
        T1[t] = s;
    }
    __syncthreads();
    if (t < 324) {                              // A^3
        double s = 0.0;
        for (int k = 0; k < NS; k++) s += T1[i * NS + k] * A[k * NS + j];
        T2[t] = s;
    }
    __syncthreads();
    if (t < 324) {                              // Phi = I+30A+450A^2+4500A^3+33750A^4
        double a4 = 0.0;
        for (int k = 0; k < NS; k++) a4 += T2[i * NS + k] * A[k * NS + j];
        double ph = (i == j ? 1.0 : 0.0) + 30.0 * A[t] + 450.0 * T1[t]
                  + 4500.0 * T2[t] + 33750.0 * a4;
        PH[t] = ph;
        g_Phi[t] = (float)ph;
    }
    if (t < NS) {                               // forcing basis + M
        double r1 = 0, r2 = 0, r3 = 0, u1 = 0, u2 = 0, u3 = 0;
        for (int k = 0; k < NS; k++) { r1 += A[t * NS + k] * vr[k];  u1 += A[t * NS + k] * vt[k]; }
        for (int k = 0; k < NS; k++) { r2 += T1[t * NS + k] * vr[k]; u2 += T1[t * NS + k] * vt[k]; }
        for (int k = 0; k < NS; k++) { r3 += T2[t * NS + k] * vr[k]; u3 += T2[t * NS + k] * vt[k]; }
        Md[t]  = 30.0 * vr[t] + 450.0 * r1 + 4500.0 * r2 + 33750.0 * r3;
        P1d[t] =  5.0 * vt[t] + 150.0 * u1 + 2250.0 * u2 + 33750.0 * u3;
        Pmd[t] = 20.0 * vt[t] + 300.0 * u1 + 2250.0 * u2;
        Pnd[t] =  5.0 * vt[t];
        g_P1[t] = (float)P1d[t]; g_Pm[t] = (float)Pmd[t]; g_Pn[t] = (float)Pnd[t];
    }
    __syncthreads();
    if (t < 324) {                              // Phi^2
        double s = 0.0;
        for (int k = 0; k < NS; k++) s += PH[i * NS + k] * PH[k * NS + j];
        PH2[t] = s;
    }
    if (t < 288) {                              // G @ Phi
        int m = t / NS, jj = t % NS;
        double s = 0.0;
        for (int k = 0; k < NS; k++) s += G[m * NS + k] * PH[k * NS + jj];
        GP[t] = s;
        g_G[t] = (float)G[t];
    }
    __syncthreads();
    if (t < NS) {
        double a2 = 0, a1 = 0, q1 = 0, qm = 0, qn = 0;
        for (int k = 0; k < NS; k++) {
            a2 += PH2[t * NS + k] * Md[k];
            a1 += PH[t * NS + k] * Md[k];
            q1 += PH[t * NS + k] * P1d[k];
            qm += PH[t * NS + k] * Pmd[k];
            qn += PH[t * NS + k] * Pnd[k];
        }
        g_hA2[t] = (float)(0.5 * a2);
        g_hA1[t] = (float)(0.5 * a1);
        g_hM[t]  = (float)(0.5 * Md[t]);
        g_PhP1[t] = (float)q1; g_PhPm[t] = (float)qm; g_PhPn[t] = (float)qn;
    }
    if (t < NH) {
        double b2v = 0, b1v = 0, e1 = 0, em = 0, en = 0, srow = 0;
        for (int k = 0; k < NS; k++) {
            b2v += GP[t * NS + k] * Md[k];
            b1v += G[t * NS + k]  * Md[k];
            e1  += G[t * NS + k]  * P1d[k];
            em  += G[t * NS + k]  * Pmd[k];
            en  += G[t * NS + k]  * Pnd[k];
            srow += G[t * NS + k];
        }
        g_hB2[t] = (float)(0.5 * b2v);
        g_hB1[t] = (float)(0.5 * b1v);
        g_GP1[t] = (float)e1; g_GPm[t] = (float)em; g_GPn[t] = (float)en;
        g_cb[t]   = (float)((double)b1[t] - 23.359 * srow);   // b1 - mu*sum(Grow)
        g_wtow[t] = W1[t * 20 + 18];
        g_wtod[t] = W1[t * 20 + 19];
        g_w2m[t]  = (float)((double)w2[t] * s_scl);
    }
    __syncthreads();
    if (t < 576) {                              // packed rows for the scan
        int lane = t / NS, jj = t % NS;
        float lo = (lane < NS) ? (float)PH2[lane * NS + jj] : 0.0f;
        float hf = (float)GP[(lane & (NH - 1)) * NS + jj];
        g_PK[lane * NS + jj] = ((ull)__float_as_uint(hf) << 32) | (ull)__float_as_uint(lo);
    }
}

// ---------------- kernel 1: per-step packed records ----------------------
// W_k = w_k + Phi*w_{k-1} + .5*Phi2M + .5*PhiM   (state const, low half)
// C_k = c_k + G*w_{k-1}   + .5*GPhiM + .5*GM     (policy const, high half)
__global__ void k_steps(const float* __restrict__ t_eval, const float* __restrict__ Tt)
{
    int step = blockIdx.x * (blockDim.x >> 5) + (threadIdx.x >> 5);
    int lane = threadIdx.x & 31;
    if (step >= NSTEP) return;

    float tau1 = Tt[step], taun = Tt[step + 1];
    float taum = 0.5f * (tau1 + taun);
    int   sm1  = (step > 0) ? (step - 1) : 0;
    float tp1  = Tt[sm1], tpn = Tt[sm1 + 1];
    float tpm  = 0.5f * (tp1 + tpn);
    float t    = t_eval[step];
    float tod  = fmodf(t, 86400.0f) * (1.0f / 86400.0f);
    float tow  = fmodf(t + 259200.0f, 604800.0f) * (1.0f / 604800.0f);

    float Wl = 0.0f;
    if (lane < NS)
        Wl = tau1 * g_P1[lane] + taum * g_Pm[lane] + taun * g_Pn[lane]
           + tp1 * g_PhP1[lane] + tpm * g_PhPm[lane] + tpn * g_PhPn[lane]
           + g_hA2[lane] + g_hA1[lane];
    int hi = lane & (NH - 1);
    float Cl = g_cb[hi] + g_wtow[hi] * tow + g_wtod[hi] * tod
             + tp1 * g_GP1[hi] + tpm * g_GPm[hi] + tpn * g_GPn[hi]
             + g_hB2[hi] + g_hB1[hi];

    g_rec2[step * 32 + lane] = ((ull)__float_as_uint(Cl) << 32) | (ull)__float_as_uint(Wl);
}

// ---------------- kernel 2: sequential scan, warp-per-batch --------------
// One step. RQ: record reg (self-replacing, depth-4 queue). AC: packed matvec
// acc (depth-2). THa/THb: dup'd th regs (THa = th_{k-2}, THb = th_{k-1}); new
// th overwrites THa. SZB: smem z buffer for this step parity. PFO: prefetch
// element offset from rq.
#define STEP(RQ, AC, THa, THb, SZB, PFO) do {                                 \
    ull ZS_; ADD2(ZS_, AC, RQ);                /* (u+Wk, v+Ck) */             \
    FMA2(ZS_, THa, HAB2);                                                     \
    FMA2(ZS_, THb, HAB1);                                                     \
    float z_, s_; UNPACK2(z_, s_, ZS_);                                       \
    if (sl) (SZB)[lane] = make_float2(z_, z_);                                \
    __syncwarp();                                                             \
    { ull a0_ = 0ull, a1_ = 0ull;              /* fills REDUX shadow */       \
      const ulonglong2* zp_ = (const ulonglong2*)(SZB);                       \
      _Pragma("unroll")                                                       \
      for (int p_ = 0; p_ < 9; p_++) {                                        \
          ulonglong2 q_ = zp_[p_];             /* LDS.128: two dup pairs */   \
          FMA2(a0_, PK[2 * p_],     q_.x);                                    \
          FMA2(a1_, PK[2 * p_ + 1], q_.y);                                    \
      }                                                                       \
      ADD2(AC, a0_, a1_); }                                                   \
    float th_; POLICYM(th_, s_);                                              \
    PACKDUP(THa, th_);                                                        \
    float x_ = fmaf(th_, hM, z_ + hM);         /* x = z + (.5+.5th)*M */      \
    if (sl) op[lane] = x_;                                                    \
    op += BATCH * NS;                                                         \
    RQ = rq[PFO];                                                             \
} while (0)

__global__ void __launch_bounds__(32, 1)
k_scan(const float* __restrict__ iv, const float* __restrict__ t_eval,
       const float* __restrict__ Tt, float* __restrict__ out)
{
    __shared__ __align__(16) float2 szbuf[2][20];
    int b = blockIdx.x, lane = threadIdx.x, hi = lane & (NH - 1);
    bool sl = (lane < NS);

    ull PK[NS];
#pragma unroll
    for (int j = 0; j < NS; j++) PK[j] = g_PK[lane * NS + j];
    float hM  = sl ? g_hM[lane] : 0.f;
    float w2m = g_w2m[hi];
    float sclv = g_sclv, cbr = g_cbr;
    ull HAB2, HAB1;
    {
        float a2v = sl ? g_hA2[lane] : 0.f, b2v = g_hB2[hi];
        float a1v = sl ? g_hA1[lane] : 0.f, b1v = g_hB1[hi];
        PACK2(HAB2, a2v, b2v);
        PACK2(HAB1, a1v, b1v);
    }

    // prologue-only rows
    float Ph[NS], Gr[NS];
#pragma unroll
    for (int j = 0; j < NS; j++) {
        Ph[j] = sl ? g_Phi[lane * NS + j] : 0.f;
        Gr[j] = g_G[hi * NS + j];
    }
    float P1l = sl ? g_P1[lane] : 0.f, Pml = sl ? g_Pm[lane] : 0.f, Pnl = sl ? g_Pn[lane] : 0.f;
    float cbl = g_cb[hi], wtowl = g_wtow[hi], wtodl = g_wtod[hi];

    float x0 = sl ? iv[b * NS + lane] : 0.f;
    if (sl) out[b * NS + lane] = x0;                        // row 0 = iv

    // ---- step 0 (direct) ----
    float ta = Tt[0], tb = Tt[1], tm = 0.5f * (ta + tb);
    float w0 = ta * P1l + tm * Pml + tb * Pnl;
    float tv = t_eval[0];
    float tod = fmodf(tv, 86400.0f) * (1.0f / 86400.0f);
    float tow = fmodf(tv + 259200.0f, 604800.0f) * (1.0f / 604800.0f);
    float s0 = cbl + wtowl * tow + wtodl * tod, z0 = w0;
#pragma unroll
    for (int j = 0; j < NS; j++) {
        float xj = __shfl_sync(0xffffffffu, x0, j);
        s0 = fmaf(Gr[j], xj, s0);
        z0 = fmaf(Ph[j], xj, z0);
    }
    float th0; POLICYM(th0, s0);
    float x1 = fmaf(th0, hM, z0 + hM);
    if (sl) out[1 * BATCH * NS + b * NS + lane] = x1;

    // ---- step 1 (direct) ----
    ta = Tt[1]; tb = Tt[2]; tm = 0.5f * (ta + tb);
    float w1 = ta * P1l + tm * Pml + tb * Pnl;
    tv = t_eval[1];
    tod = fmodf(tv, 86400.0f) * (1.0f / 86400.0f);
    tow = fmodf(tv + 259200.0f, 604800.0f) * (1.0f / 604800.0f);
    float s1 = cbl + wtowl * tow + wtodl * tod, z1 = w1;
#pragma unroll
    for (int j = 0; j < NS; j++) {
        float xj = __shfl_sync(0xffffffffu, x1, j);
        s1 = fmaf(Gr[j], xj, s1);
        z1 = fmaf(Ph[j], xj, z1);
    }
    float th1; POLICYM(th1, s1);
    float x2 = fmaf(th1, hM, z1 + hM);
    if (sl) out[2 * BATCH * NS + b * NS + lane] = x2;

    // ---- seed packed matvecs of z0, z1 (shuffle path, once) ----
    ull AC0 = 0ull, AC1 = 0ull;
#pragma unroll
    for (int j = 0; j < NS; j++) {
        float zj = __shfl_sync(0xffffffffu, z0, j);
        ull zz; PACKDUP(zz, zj);
        FMA2(AC0, PK[j], zz);
    }
#pragma unroll
    for (int j = 0; j < NS; j++) {
        float zj = __shfl_sync(0xffffffffu, z1, j);
        ull zz; PACKDUP(zz, zj);
        FMA2(AC1, PK[j], zz);
    }

    ull THP0, THP1;
    PACKDUP(THP0, th0);            // th_{k-2} at k=2
    PACKDUP(THP1, th1);            // th_{k-1} at k=2

    // record queue: RQ0..RQ3 = records 2..5; rq points at record 6
    ull RQ0 = g_rec2[2 * 32 + lane], RQ1 = g_rec2[3 * 32 + lane];
    ull RQ2 = g_rec2[4 * 32 + lane], RQ3 = g_rec2[5 * 32 + lane];
    const ull* rq = g_rec2 + 6 * 32 + lane;

    float* op = out + 3 * BATCH * NS + b * NS;              // row 3

    // ---- single step k = 2 (aligns remaining 32764 = 4 * 8191) ----
    STEP(RQ0, AC0, THP0, THP1, szbuf[0], 0);
    rq += 32;

    // ---- steady loop: k = 3 .. 32766 ----
    for (int g = 0; g < 8191; g++) {
        STEP(RQ1, AC1, THP1, THP0, szbuf[1], 0);
        STEP(RQ2, AC0, THP0, THP1, szbuf[0], 32);
        STEP(RQ3, AC1, THP1, THP0, szbuf[1], 64);
        STEP(RQ0, AC0, THP0, THP1, szbuf[0], 96);
        rq += 128;
    }
}

// ---------------- launch ------------------------------------------------
extern "C" void kernel_launch(void* const* d_in, const int* in_sizes, int n_in,
                              void* d_out, int out_size)
{
    const float* t_eval = (const float*)d_in[0];
    const float* iv     = (const float*)d_in[1];
    const float* W_A    = (const float*)d_in[2];
    const float* W_B    = (const float*)d_in[3];
    const float* W1     = (const float*)d_in[4];
    const float* b1     = (const float*)d_in[5];
    const float* w2     = (const float*)d_in[6];
    const float* b2     = (const float*)d_in[7];
    const float* Tt     = (const float*)d_in[8];
    float* out = (float*)d_out;

    k_setup<<<1, 576>>>(W_A, W_B, W1, b1, w2, b2);
    k_steps<<<(NSTEP + 7) / 8, 256>>>(t_eval, Tt);
    k_scan<<<BATCH, 32>>>(iv, t_eval, Tt, out);
}

// round 10
// speedup vs baseline: 1.8486x; 1.1359x over previous
#include <cuda_runtime.h>
#include <cuda_bf16.h>

#define T_STEPS 32768
#define NSTEP   (T_STEPS - 1)    // 32767 RK4 steps; outputs x_1..x_32767
#define BATCH   32
#define NS      18
#define NH      16
#define FULL    0xffffffffu
typedef unsigned long long ull;

// ---------------- device scratch (static, no allocation) ----------------
__device__ float g_Phi[NS * NS];     // Phi fp32 (prologue direct steps)
__device__ float g_G[NH * NS];       // W1[:, :18]/STD (prologue)
__device__ float g_SP[9 * NS];       // state basis: {I,Phi,Phi2} x {P1,Pm,Pn}
__device__ float g_CP[6 * NH];       // policy basis: {G,GPhi} x {P1,Pm,Pn}
__device__ float g_Wc[NS], g_Cc[NH]; // .5*(Phi3+Phi2+Phi)M, .5*(GPhi2+GPhi+G)M
__device__ float g_hA1[NS], g_hA2[NS], g_hA3[NS];   // .5*Phi^d M
__device__ float g_hB1[NH], g_hB2[NH], g_hB3[NH];   // .5*G Phi^{d-1} M
__device__ float g_hM[NS];           // .5*M
__device__ float g_cb[NH], g_wtow[NH], g_wtod[NH];
__device__ float g_w2m[NH];          // w2 * SCL (adaptive fixed-point scale)
__device__ float g_sclv;             // 1/(4*SCL)
__device__ float g_cbr;              // b2/2 - MAGICF/(4*SCL)
__device__ ull   g_PK[32 * NS];      // packed rows: lo=Phi3[lane], hi=GPhi2[lane&15]
__device__ ull   g_rec2[(NSTEP + 8) * 32];  // packed per-step record (W_k, C_k)

// ---------------- packed f32x2 / activation helpers ----------------------
#define FMA2(acc, a, b)  asm("fma.rn.f32x2 %0, %1, %2, %0;" : "+l"(acc) : "l"(a), "l"(b))
#define PACKDUP(d, s)    asm("mov.b64 %0, {%1, %1};" : "=l"(d) : "f"(s))
#define PACK2(d, lo, hi) asm("mov.b64 %0, {%1, %2};" : "=l"(d) : "f"(lo), "f"(hi))
#define UNPACK2(lo, hi, v) asm("mov.b64 {%0, %1}, %2;" : "=f"(lo), "=f"(hi) : "l"(v))
#define ADD2(d, a, b)    asm("add.rn.f32x2 %0, %1, %2;" : "=l"(d) : "l"(a), "l"(b))
#define TANHA(d, s)      asm("tanh.approx.f32 %0, %1;" : "=f"(d) : "f"(s))
#define BARRIER()        asm volatile("bar.sync 0;" ::: "memory")

// ---- policy: th = tanh((w2 . tanh(s) + b2)/2) via magic-number fixed point
#define MAGICF 12582912.0f
#define KADJ   (0u - 31u * 0x4B400000u)
#define POLICYM(th_out, s_in) do {                                            \
    float h_; TANHA(h_, (s_in));                                              \
    float fb_ = fmaf(h_, w2m, MAGICF);                                        \
    unsigned su_ = __reduce_add_sync(FULL, __float_as_uint(fb_));             \
    float af_ = __uint_as_float(su_ + KADJ);                                  \
    float a_ = fmaf(af_, sclv, cbr);                                          \
    TANHA((th_out), a_);                                                      \
} while (0)

// ---------------- kernel 0: constants, fp64, 576 threads -----------------
__global__ void k_setup(const float* __restrict__ W_A, const float* __restrict__ W_B,
                        const float* __restrict__ W1, const float* __restrict__ b1,
                        const float* __restrict__ w2, const float* __restrict__ b2)
{
    __shared__ double A[324], T1[324], T2[324], PH[324], PH2[324];
    __shared__ double G[288], GP[288];
    __shared__ double vt[NS], vr[NS], Md[NS], P1d[NS], Pmd[NS], Pnd[NS];
    __shared__ double s_scl;
    int t = threadIdx.x;
    int i = t / NS, j = t % NS;

    if (t < 324) A[t] = 1e-4 * (double)W_A[t] - (i == j ? 1e-3 : 0.0);
    if (t < NS) {
        vt[t] = 1e-6 * (double)W_B[t * 17 + 0];
        double s = 0.0;
        for (int c = 1; c < 17; c++) s += (double)W_B[t * 17 + c];
        vr[t] = s * (-16914.0 * 1e-6);
    }
    if (t < 288) G[t] = (double)W1[(t / NS) * 20 + (t % NS)] / 1.41;
    if (t == 0) {
        double ss = 0.0;
        for (int k = 0; k < NH; k++) ss += fabs((double)w2[k]);
        double SCL = exp2(floor(20.0 - log2(ss > 1.0 ? ss : 1.0)));
        s_scl  = SCL;
        g_sclv = (float)(1.0 / (4.0 * SCL));
        g_cbr  = (float)(0.5 * (double)b2[0] - (double)MAGICF / (4.0 * SCL));
    }
    __syncthreads();
    if (t < 324) {                              // A^2
        double s = 0.0;
        for (int k = 0; k < NS; k++) s += A[i * NS + k] * A[k * NS + j];
        T1[t] = s;
    }
    __syncthreads();
    if (t < 324) {                              // A^3
        double s = 0.0;
        for (int k = 0; k < NS; k++) s += T1[i * NS + k] * A[k * NS + j];
        T2[t] = s;
    }
    __syncthreads();
    if (t < 324) {                              // Phi = I+30A+450A^2+4500A^3+33750A^4
        double a4 = 0.0;
        for (int k = 0; k < NS; k++) a4 += T2[i * NS + k] * A[k * NS + j];
        double ph = (i == j ? 1.0 : 0.0) + 30.0 * A[t] + 450.0 * T1[t]
                  + 4500.0 * T2[t] + 33750.0 * a4;
        PH[t] = ph;
        g_Phi[t] = (float)ph;
    }
    if (t < NS) {                               // forcing basis + M
        double r1 = 0, r2 = 0, r3 = 0, u1 = 0, u2 = 0, u3 = 0;
        for (int k = 0; k < NS; k++) { r1 += A[t * NS + k] * vr[k];  u1 += A[t * NS + k] * vt[k]; }
        for (int k = 0; k < NS; k++) { r2 += T1[t * NS + k] * vr[k]; u2 += T1[t * NS + k] * vt[k]; }
        for (int k = 0; k < NS; k++) { r3 += T2[t * NS + k] * vr[k]; u3 += T2[t * NS + k] * vt[k]; }
        Md[t]  = 30.0 * vr[t] + 450.0 * r1 + 4500.0 * r2 + 33750.0 * r3;
        P1d[t] =  5.0 * vt[t] + 150.0 * u1 + 2250.0 * u2 + 33750.0 * u3;
        Pmd[t] = 20.0 * vt[t] + 300.0 * u1 + 2250.0 * u2;
        Pnd[t] =  5.0 * vt[t];
        g_SP[0 * NS + t] = (float)P1d[t];
        g_SP[1 * NS + t] = (float)Pmd[t];
        g_SP[2 * NS + t] = (float)Pnd[t];
        g_hM[t] = (float)(0.5 * Md[t]);
    }
    __syncthreads();
    if (t < 324) {                              // Phi^2
        double s = 0.0;
        for (int k = 0; k < NS; k++) s += PH[i * NS + k] * PH[k * NS + j];
        PH2[t] = s;
    }
    if (t < 288) {                              // G @ Phi
        int m = t / NS, jj = t % NS;
        double s = 0.0;
        for (int k = 0; k < NS; k++) s += G[m * NS + k] * PH[k * NS + jj];
        GP[t] = s;
        g_G[t] = (float)G[t];
    }
    __syncthreads();
    if (t < 324) {                              // Phi^3 -> T2 (A^3 dead)
        double s = 0.0;
        for (int k = 0; k < NS; k++) s += PH2[i * NS + k] * PH[k * NS + j];
        T2[t] = s;
    }
    if (t < 288) {                              // G Phi^2 -> T1 (A^2 dead)
        int m = t / NS, jj = t % NS;
        double s = 0.0;
        for (int k = 0; k < NS; k++) s += GP[m * NS + k] * PH[k * NS + jj];
        T1[t] = s;
    }
    __syncthreads();
    if (t < NS) {                               // state-side vectors
        double a1 = 0, a2 = 0, a3 = 0;
        double b1v = 0, bm = 0, bn = 0, c1v = 0, cm = 0, cn = 0;
        for (int k = 0; k < NS; k++) {
            a1  += PH[t * NS + k]  * Md[k];
            a2  += PH2[t * NS + k] * Md[k];
            a3  += T2[t * NS + k]  * Md[k];
            b1v += PH[t * NS + k]  * P1d[k];
            bm  += PH[t * NS + k]  * Pmd[k];
            bn  += PH[t * NS + k]  * Pnd[k];
            c1v += PH2[t * NS + k] * P1d[k];
            cm  += PH2[t * NS + k] * Pmd[k];
            cn  += PH2[t * NS + k] * Pnd[k];
        }
        g_hA1[t] = (float)(0.5 * a1);
        g_hA2[t] = (float)(0.5 * a2);
        g_hA3[t] = (float)(0.5 * a3);
        g_Wc[t]  = (float)(0.5 * (a1 + a2 + a3));
        g_SP[3 * NS + t] = (float)b1v;
        g_SP[4 * NS + t] = (float)bm;
        g_SP[5 * NS + t] = (float)bn;
        g_SP[6 * NS + t] = (float)c1v;
        g_SP[7 * NS + t] = (float)cm;
        g_SP[8 * NS + t] = (float)cn;
    }
    if (t < NH) {                               // policy-side vectors
        double h1 = 0, h2 = 0, h3 = 0, srow = 0;
        double e0p = 0, e0m = 0, e0n = 0, e1p = 0, e1m = 0, e1n = 0;
        for (int k = 0; k < NS; k++) {
            h1  += G[t * NS + k]  * Md[k];
            h2  += GP[t * NS + k] * Md[k];
            h3  += T1[t * NS + k] * Md[k];
            e0p += G[t * NS + k]  * P1d[k];
            e0m += G[t * NS + k]  * Pmd[k];
            e0n += G[t * NS + k]  * Pnd[k];
            e1p += GP[t * NS + k] * P1d[k];
            e1m += GP[t * NS + k] * Pmd[k];
            e1n += GP[t * NS + k] * Pnd[k];
            srow += G[t * NS + k];
        }
        g_hB1[t] = (float)(0.5 * h1);
        g_hB2[t] = (float)(0.5 * h2);
        g_hB3[t] = (float)(0.5 * h3);
        g_Cc[t]  = (float)(0.5 * (h1 + h2 + h3));
        g_CP[0 * NH + t] = (float)e0p;
        g_CP[1 * NH + t] = (float)e0m;
        g_CP[2 * NH + t] = (float)e0n;
        g_CP[3 * NH + t] = (float)e1p;
        g_CP[4 * NH + t] = (float)e1m;
        g_CP[5 * NH + t] = (float)e1n;
        g_cb[t]   = (float)((double)b1[t] - 23.359 * srow);
        g_wtow[t] = W1[t * 20 + 18];
        g_wtod[t] = W1[t * 20 + 19];
        g_w2m[t]  = (float)((double)w2[t] * s_scl);
    }
    __syncthreads();
    if (t < 576) {                              // packed rows: Phi3 | GPhi2
        int lane = t / NS, jj = t % NS;
        float lo = (lane < NS) ? (float)T2[lane * NS + jj] : 0.0f;
        float hf = (float)T1[(lane & (NH - 1)) * NS + jj];
        g_PK[lane * NS + jj] = ((ull)__float_as_uint(hf) << 32) | (ull)__float_as_uint(lo);
    }
}

// ---------------- kernel 1: per-step packed records (depth-3) ------------
// W_k = w_k + Phi w_{k-1} + Phi2 w_{k-2} + .5(Phi3+Phi2+Phi)M
// C_k = c_k + G w_{k-1} + GPhi w_{k-2} + .5(GPhi2+GPhi+G)M
__global__ void k_steps(const float* __restrict__ t_eval, const float* __restrict__ Tt)
{
    int step = blockIdx.x * (blockDim.x >> 5) + (threadIdx.x >> 5);
    int lane = threadIdx.x & 31;
    if (step >= NSTEP) return;

    float t1a = Tt[step], tna = Tt[step + 1], tma = 0.5f * (t1a + tna);
    int k1 = (step > 0) ? step - 1 : 0;
    float t1b = Tt[k1], tnb = Tt[k1 + 1], tmb = 0.5f * (t1b + tnb);
    int k2 = (step > 1) ? step - 2 : 0;
    float t1c = Tt[k2], tnc = Tt[k2 + 1], tmc = 0.5f * (t1c + tnc);

    float t   = t_eval[step];
    float tod = fmodf(t, 86400.0f) * (1.0f / 86400.0f);
    float tow = fmodf(t + 259200.0f, 604800.0f) * (1.0f / 604800.0f);

    float Wl = 0.0f;
    if (lane < NS)
        Wl = t1a * g_SP[0 * NS + lane] + tma * g_SP[1 * NS + lane] + tna * g_SP[2 * NS + lane]
           + t1b * g_SP[3 * NS + lane] + tmb * g_SP[4 * NS + lane] + tnb * g_SP[5 * NS + lane]
           + t1c * g_SP[6 * NS + lane] + tmc * g_SP[7 * NS + lane] + tnc * g_SP[8 * NS + lane]
           + g_Wc[lane];
    int hi = lane & (NH - 1);
    float Cl = g_cb[hi] + g_wtow[hi] * tow + g_wtod[hi] * tod
             + t1b * g_CP[0 * NH + hi] + tmb * g_CP[1 * NH + hi] + tnb * g_CP[2 * NH + hi]
             + t1c * g_CP[3 * NH + hi] + tmc * g_CP[4 * NH + hi] + tnc * g_CP[5 * NH + hi]
             + g_Cc[hi];

    g_rec2[step * 32 + lane] = ((ull)__float_as_uint(Cl) << 32) | (ull)__float_as_uint(Wl);
}

// ---------------- kernel 2: warp-specialized scan, 2 warps per batch -----
// Warp 0 (A): serial chain (policy + state update + store).
// Warp 1 (B): dual packed matvec (Phi3 z, GPhi2 z) one z behind A.
// One bar.sync per step; double-buffered z and AC in smem.

// A's step k: consume ACc = AC3(z_{k-3}); load ACl <- acbuf[ACSLOT] (B's write
// at k-1 = AC3(z_{k-2}), consumed at k+1). Record RQ self-replacing depth-4.
#define STEP_A(THn, TH1, TH2, TH3, ACc, ACl, ZSLOT, ACSLOT, RQ, PFO) do {     \
    ull ZS_; ADD2(ZS_, ACc, RQ);                                              \
    FMA2(ZS_, TH3, HAB3);                                                     \
    FMA2(ZS_, TH2, HAB2);                                                     \
    FMA2(ZS_, TH1, HAB1);                                                     \
    float z_, s_; UNPACK2(z_, s_, ZS_);                                       \
    if (sl) zbuf[ZSLOT][lane] = make_float2(z_, z_);                          \
    ACl = acbuf[ACSLOT][lane];                                                \
    float th_; POLICYM(th_, s_);                                              \
    PACKDUP(THn, th_);                                                        \
    float x_ = fmaf(th_, hM, z_ + hM);                                        \
    if (sl) op[lane] = x_;                                                    \
    op += BATCH * NS;                                                         \
    RQ = rq[PFO];                                                             \
    BARRIER();                                                                \
} while (0)

// B's step: broadcast z via 9x LDS.128 (dup pairs), 18 packed FMA into 4 accs.
#define STEP_B(ZQ, ABUF) do {                                                 \
    ull a0_ = 0ull, a1_ = 0ull, a2_ = 0ull, a3_ = 0ull;                       \
    _Pragma("unroll")                                                         \
    for (int p_ = 0; p_ < 9; p_++) {                                          \
        ulonglong2 q_ = (ZQ)[p_];                                             \
        if (p_ & 1) { FMA2(a2_, PK[2 * p_], q_.x); FMA2(a3_, PK[2 * p_ + 1], q_.y); } \
        else        { FMA2(a0_, PK[2 * p_], q_.x); FMA2(a1_, PK[2 * p_ + 1], q_.y); } \
    }                                                                         \
    ull t0_, t1_, ac_;                                                        \
    ADD2(t0_, a0_, a2_); ADD2(t1_, a1_, a3_); ADD2(ac_, t0_, t1_);            \
    (ABUF)[lane] = ac_;                                                       \
    BARRIER();                                                                \
} while (0)

__global__ void __launch_bounds__(64, 1)
k_scan(const float* __restrict__ iv, const float* __restrict__ t_eval,
       const float* __restrict__ Tt, float* __restrict__ out)
{
    __shared__ __align__(16) float2 zbuf[2][20];
    __shared__ __align__(16) ull acbuf[2][32];
    int b = blockIdx.x;
    int tid = threadIdx.x;
    int wid = tid >> 5, lane = tid & 31, hi = lane & (NH - 1);
    bool sl = (lane < NS);

    ull PK[NS];
#pragma unroll
    for (int j = 0; j < NS; j++) PK[j] = g_PK[lane * NS + j];

    if (wid == 1) {
        // ======== warp B: matvec engine ========
        BARRIER();                                  // pre-loop
        const ulonglong2* zq0 = (const ulonglong2*)&zbuf[0][0];
        const ulonglong2* zq1 = (const ulonglong2*)&zbuf[1][0];
        for (int g = 0; g < 16382; g++) {           // 2 steps per iter = 32764
            STEP_B(zq0, &acbuf[1][0]);              // k odd:  read z_{k-1}@zbuf0
            STEP_B(zq1, &acbuf[0][0]);              // k even: read z_{k-1}@zbuf1
        }
        return;
    }

    // ======== warp A: sequential chain ========
    float hM  = sl ? g_hM[lane] : 0.f;
    float w2m = g_w2m[hi];
    float sclv = g_sclv, cbr = g_cbr;
    ull HAB1, HAB2, HAB3;
    {
        float a1 = sl ? g_hA1[lane] : 0.f, b1v = g_hB1[hi];
        float a2 = sl ? g_hA2[lane] : 0.f, b2v = g_hB2[hi];
        float a3 = sl ? g_hA3[lane] : 0.f, b3v = g_hB3[hi];
        PACK2(HAB1, a1, b1v);
        PACK2(HAB2, a2, b2v);
        PACK2(HAB3, a3, b3v);
    }
    float Ph[NS], Gr[NS];
#pragma unroll
    for (int j = 0; j < NS; j++) {
        Ph[j] = sl ? g_Phi[lane * NS + j] : 0.f;
        Gr[j] = g_G[hi * NS + j];
    }
    float P1l = sl ? g_SP[0 * NS + lane] : 0.f;
    float Pml = sl ? g_SP[1 * NS + lane] : 0.f;
    float Pnl = sl ? g_SP[2 * NS + lane] : 0.f;
    float cbl = g_cb[hi], wtowl = g_wtow[hi], wtodl = g_wtod[hi];

    float x = sl ? iv[b * NS + lane] : 0.f;
    if (sl) out[b * NS + lane] = x;                 // row 0 = iv

    // ---- direct steps 0,1,2 (shuffle matvec) ----
    float zarr[3], tharr[3];
#pragma unroll
    for (int j = 0; j < 3; j++) {
        float ta = Tt[j], tb = Tt[j + 1], tm = 0.5f * (ta + tb);
        float w = ta * P1l + tm * Pml + tb * Pnl;
        float tv = t_eval[j];
        float tod = fmodf(tv, 86400.0f) * (1.0f / 86400.0f);
        float tow = fmodf(tv + 259200.0f, 604800.0f) * (1.0f / 604800.0f);
        float s = cbl + wtowl * tow + wtodl * tod, z = w;
#pragma unroll
        for (int q = 0; q < NS; q++) {
            float xq = __shfl_sync(FULL, x, q);
            s = fmaf(Gr[q], xq, s);
            z = fmaf(Ph[q], xq, z);
        }
        float th; POLICYM(th, s);
        x = fmaf(th, hM, z + hM);
        if (sl) out[(j + 1) * BATCH * NS + b * NS + lane] = x;
        zarr[j] = z; tharr[j] = th;
    }

    // ---- seed AC3(z0), AC3(z1) via shuffle on PK rows ----
    ull AC0 = 0ull, AC1 = 0ull, AC31 = 0ull;
#pragma unroll
    for (int j = 0; j < NS; j++) {
        float zj = __shfl_sync(FULL, zarr[0], j);
        ull zz; PACKDUP(zz, zj);
        FMA2(AC0, PK[j], zz);                       // AC3(z0) -> consumed k=3
    }
#pragma unroll
    for (int j = 0; j < NS; j++) {
        float zj = __shfl_sync(FULL, zarr[1], j);
        ull zz; PACKDUP(zz, zj);
        FMA2(AC31, PK[j], zz);                      // AC3(z1) -> via acbuf[0]
    }
    acbuf[0][lane] = AC31;
    if (sl) zbuf[0][lane] = make_float2(zarr[2], zarr[2]);   // z2 for B @ k=3

    ull THa, THb, THc, THd = 0ull;
    PACKDUP(THa, tharr[0]); PACKDUP(THb, tharr[1]); PACKDUP(THc, tharr[2]);

    ull RQ0 = g_rec2[3 * 32 + lane], RQ1 = g_rec2[4 * 32 + lane];
    ull RQ2 = g_rec2[5 * 32 + lane], RQ3 = g_rec2[6 * 32 + lane];
    const ull* rq = g_rec2 + 7 * 32 + lane;
    float* op = out + 4 * BATCH * NS + b * NS;      // rows 4..32767

    BARRIER();                                      // pre-loop

    // ---- steady loop: k = 3 .. 32766  (32764 = 4 * 8191) ----
    for (int g = 0; g < 8191; g++) {
        STEP_A(THd, THc, THb, THa, AC0, AC1, 1, 0, RQ0, 0);
        STEP_A(THa, THd, THc, THb, AC1, AC0, 0, 1, RQ1, 32);
        STEP_A(THb, THa, THd, THc, AC0, AC1, 1, 0, RQ2, 64);
        STEP_A(THc, THb, THa, THd, AC1, AC0, 0, 1, RQ3, 96);
        rq += 128;
    }
}

// ---------------- launch ------------------------------------------------
extern "C" void kernel_launch(void* const* d_in, const int* in_sizes, int n_in,
                              void* d_out, int out_size)
{
    const float* t_eval = (const float*)d_in[0];
    const float* iv     = (const float*)d_in[1];
    const float* W_A    = (const float*)d_in[2];
    const float* W_B    = (const float*)d_in[3];
    const float* W1     = (const float*)d_in[4];
    const float* b1     = (const float*)d_in[5];
    const float* w2     = (const float*)d_in[6];
    const float* b2     = (const float*)d_in[7];
    const float* Tt     = (const float*)d_in[8];
    float* out = (float*)d_out;

    k_setup<<<1, 576>>>(W_A, W_B, W1, b1, w2, b2);
    k_steps<<<(NSTEP + 7) / 8, 256>>>(t_eval, Tt);
    k_scan<<<BATCH, 64>>>(iv, t_eval, Tt, out);
}

// round 13
// speedup vs baseline: 2.1512x; 1.1637x over previous
#include <cuda_runtime.h>

#define T_STEPS 32768
#define NSTEP   (T_STEPS - 1)    // 32767 RK4 steps; outputs x_1..x_32767
#define BATCH   32
#define NS      18
#define NH      16
#define FULL    0xffffffffu
typedef unsigned long long ull;

// ---------------- device scratch (static, no allocation) ----------------
__device__ float g_Phi[NS * NS];      // Phi fp32 (prologue direct steps)
__device__ float g_G[NH * NS];        // W1[:, :18]/STD (prologue)
__device__ float g_SP[18 * NS];       // state basis: Phi^d P*, d=0..5
__device__ float g_CP[15 * NH];       // policy basis: G Phi^{d-1} P*, d=1..5
__device__ float g_Wc[NS], g_Cc[NH];  // .5*sum Phi^d M / .5*sum G Phi^{d-1} M
__device__ float g_hA[6][NS];         // .5*Phi^d M, d=1..6  ([d-1])
__device__ float g_hB[6][NH];         // .5*G Phi^{d-1} M, d=1..6
__device__ float g_hM[NS];            // .5*M
__device__ float g_cb[NH], g_wtow[NH], g_wtod[NH];
__device__ float g_w2m[NH];           // w2 * SCL
__device__ float g_sclv, g_cbr;
__device__ ull   g_PK[32 * NS];       // packed rows: lo=Phi6[lane], hi=GPhi5[lane&15]
__device__ ull   g_rec2[(NSTEP + 16) * 32];

// ---------------- packed f32x2 / activation helpers ----------------------
#define FMA2(acc, a, b)  asm("fma.rn.f32x2 %0, %1, %2, %0;" : "+l"(acc) : "l"(a), "l"(b))
#define PACKDUP(d, s)    asm("mov.b64 %0, {%1, %1};" : "=l"(d) : "f"(s))
#define PACK2(d, lo, hi) asm("mov.b64 %0, {%1, %2};" : "=l"(d) : "f"(lo), "f"(hi))
#define UNPACK2(lo, hi, v) asm("mov.b64 {%0, %1}, %2;" : "=f"(lo), "=f"(hi) : "l"(v))
#define ADD2(d, a, b)    asm("add.rn.f32x2 %0, %1, %2;" : "=l"(d) : "l"(a), "l"(b))
#define TANHA(d, s)      asm("tanh.approx.f32 %0, %1;" : "=f"(d) : "f"(s))
#define BARRIER()        asm volatile("bar.sync 0;" ::: "memory")

#define MAGICF 12582912.0f
#define KADJ   (0u - 31u * 0x4B400000u)
#define POLICYM(th_out, s_in) do {                                            \
    float h_; TANHA(h_, (s_in));                                              \
    float fb_ = fmaf(h_, w2m, MAGICF);                                        \
    unsigned su_ = __reduce_add_sync(FULL, __float_as_uint(fb_));             \
    float af_ = __uint_as_float(su_ + KADJ);                                  \
    float a_ = fmaf(af_, sclv, cbr);                                          \
    TANHA((th_out), a_);                                                      \
} while (0)

// ---------------- kernel 0: constants, fp64, 576 threads -----------------
__global__ void __launch_bounds__(576)
k_setup(const float* __restrict__ W_A, const float* __restrict__ W_B,
        const float* __restrict__ W1, const float* __restrict__ b1,
        const float* __restrict__ w2, const float* __restrict__ b2)
{
    __shared__ double A[324], T1[324], T2[324];
    __shared__ double PH[6][324];    // Phi^{d+1}
    __shared__ double GM[6][288];    // G Phi^d
    __shared__ double vt[NS], vr[NS], Md[NS], Pd[3][NS];
    __shared__ double s_scl;
    int t = threadIdx.x;
    int i = t / NS, j = t % NS;

    if (t < 324) A[t] = 1e-4 * (double)W_A[t] - (i == j ? 1e-3 : 0.0);
    if (t < NS) {
        vt[t] = 1e-6 * (double)W_B[t * 17 + 0];
        double s = 0.0;
        for (int c = 1; c < 17; c++) s += (double)W_B[t * 17 + c];
        vr[t] = s * (-16914.0 * 1e-6);
    }
    if (t < 288) GM[0][t] = (double)W1[(t / NS) * 20 + (t % NS)] / 1.41;
    if (t == 0) {
        double ss = 0.0;
        for (int k = 0; k < NH; k++) ss += fabs((double)w2[k]);
        double SCL = exp2(floor(20.0 - log2(ss > 1.0 ? ss : 1.0)));
        s_scl  = SCL;
        g_sclv = (float)(1.0 / (4.0 * SCL));
        g_cbr  = (float)(0.5 * (double)b2[0] - 12582912.0 / (4.0 * SCL));
    }
    __syncthreads();
    if (t < 324) { double s = 0; for (int k = 0; k < NS; k++) s += A[i*NS+k]*A[k*NS+j]; T1[t] = s; }
    __syncthreads();
    if (t < 324) { double s = 0; for (int k = 0; k < NS; k++) s += T1[i*NS+k]*A[k*NS+j]; T2[t] = s; }
    __syncthreads();
    if (t < 324) {
        double a4 = 0; for (int k = 0; k < NS; k++) a4 += T2[i*NS+k]*A[k*NS+j];
        PH[0][t] = (i == j ? 1.0 : 0.0) + 30.0*A[t] + 450.0*T1[t] + 4500.0*T2[t] + 33750.0*a4;
        g_Phi[t] = (float)PH[0][t];
    }
    if (t < NS) {
        double r1=0,r2=0,r3=0,u1=0,u2=0,u3=0;
        for (int k=0;k<NS;k++){ r1+=A[t*NS+k]*vr[k];  u1+=A[t*NS+k]*vt[k]; }
        for (int k=0;k<NS;k++){ r2+=T1[t*NS+k]*vr[k]; u2+=T1[t*NS+k]*vt[k]; }
        for (int k=0;k<NS;k++){ r3+=T2[t*NS+k]*vr[k]; u3+=T2[t*NS+k]*vt[k]; }
        Md[t]    = 30.0*vr[t] + 450.0*r1 + 4500.0*r2 + 33750.0*r3;
        Pd[0][t] =  5.0*vt[t] + 150.0*u1 + 2250.0*u2 + 33750.0*u3;
        Pd[1][t] = 20.0*vt[t] + 300.0*u1 + 2250.0*u2;
        Pd[2][t] =  5.0*vt[t];
        g_hM[t]  = (float)(0.5 * Md[t]);
    }
    __syncthreads();
    for (int d = 1; d < 6; d++) {                  // power chains
        if (t < 324) { double s=0; for (int k=0;k<NS;k++) s += PH[d-1][i*NS+k]*PH[0][k*NS+j]; PH[d][t]=s; }
        if (t < 288) { int m=t/NS, jj=t%NS; double s=0; for (int k=0;k<NS;k++) s += GM[d-1][m*NS+k]*PH[0][k*NS+jj]; GM[d][t]=s; }
        __syncthreads();
    }
    if (t < NS) {
        double wc = 0;
        for (int d = 1; d <= 6; d++) {
            double s = 0; for (int k = 0; k < NS; k++) s += PH[d-1][t*NS+k]*Md[k];
            g_hA[d-1][t] = (float)(0.5*s); wc += 0.5*s;
        }
        g_Wc[t] = (float)wc;
        for (int c = 0; c < 3; c++) g_SP[c*NS + t] = (float)Pd[c][t];
        for (int d = 1; d < 6; d++)
            for (int c = 0; c < 3; c++) {
                double s = 0; for (int k = 0; k < NS; k++) s += PH[d-1][t*NS+k]*Pd[c][k];
                g_SP[(3*d+c)*NS + t] = (float)s;
            }
    }
    if (t < NH) {
        double cc = 0;
        for (int d = 1; d <= 6; d++) {
            double s = 0; for (int k = 0; k < NS; k++) s += GM[d-1][t*NS+k]*Md[k];
            g_hB[d-1][t] = (float)(0.5*s); cc += 0.5*s;
        }
        g_Cc[t] = (float)cc;
        for (int d = 1; d <= 5; d++)
            for (int c = 0; c < 3; c++) {
                double s = 0; for (int k = 0; k < NS; k++) s += GM[d-1][t*NS+k]*Pd[c][k];
                g_CP[(3*(d-1)+c)*NH + t] = (float)s;
            }
        double srow = 0; for (int k = 0; k < NS; k++) srow += GM[0][t*NS+k];
        g_cb[t]   = (float)((double)b1[t] - 23.359 * srow);
        g_wtow[t] = W1[t * 20 + 18];
        g_wtod[t] = W1[t * 20 + 19];
        g_w2m[t]  = (float)((double)w2[t] * s_scl);
    }
    if (t < 288) g_G[t] = (float)GM[0][t];
    __syncthreads();
    if (t < 576) {
        int lane = t / NS, jj = t % NS;
        float lo = (lane < NS) ? (float)PH[5][lane*NS+jj] : 0.0f;   // Phi^6
        float hf = (float)GM[5][(lane & 15)*NS+jj];                 // G Phi^5
        g_PK[lane*NS + jj] = ((ull)__float_as_uint(hf) << 32) | (ull)__float_as_uint(lo);
    }
}

// ---------------- kernel 1: per-step packed records (depth-6) ------------
__global__ void k_steps(const float* __restrict__ t_eval, const float* __restrict__ Tt)
{
    int step = blockIdx.x * (blockDim.x >> 5) + (threadIdx.x >> 5);
    int lane = threadIdx.x & 31;
    if (step >= NSTEP) return;

    float t1[6], tm[6], tn[6];
#pragma unroll
    for (int d = 0; d < 6; d++) {
        int kk = step - d; if (kk < 0) kk = 0;
        t1[d] = Tt[kk]; tn[d] = Tt[kk + 1]; tm[d] = 0.5f * (t1[d] + tn[d]);
    }
    float t   = t_eval[step];
    float tod = fmodf(t, 86400.f) * (1.f / 86400.f);
    float tow = fmodf(t + 259200.f, 604800.f) * (1.f / 604800.f);

    float Wl = 0.f;
    if (lane < NS) {
        Wl = g_Wc[lane];
#pragma unroll
        for (int d = 0; d < 6; d++)
            Wl += t1[d] * g_SP[(3*d+0)*NS + lane] + tm[d] * g_SP[(3*d+1)*NS + lane]
                + tn[d] * g_SP[(3*d+2)*NS + lane];
    }
    int hi = lane & 15;
    float Cl = g_cb[hi] + g_wtow[hi] * tow + g_wtod[hi] * tod + g_Cc[hi];
#pragma unroll
    for (int d = 1; d <= 5; d++)
        Cl += t1[d] * g_CP[(3*(d-1)+0)*NH + hi] + tm[d] * g_CP[(3*(d-1)+1)*NH + hi]
            + tn[d] * g_CP[(3*(d-1)+2)*NH + hi];

    g_rec2[step * 32 + lane] = ((ull)__float_as_uint(Cl) << 32) | (ull)__float_as_uint(Wl);
}

// ---------------- kernel 2: warp-specialized scan -------------------------
// A: chain only. B: depth-6 dual matvec. 1 bar per 2 steps; AC prefetched a
// full period early (off-chain LDS).
#define STEP_A(THa, Pb, Pc, Pd_, Pe, Pf, Snew, Pnew, ACreg, Q, QOFF, ZSL, ZEN) do { \
    ull ZS_; ADD2(ZS_, ACreg, Q);                                             \
    FMA2(ZS_, Pb, HAB0); FMA2(ZS_, Pc, HAB1v); FMA2(ZS_, Pd_, HAB2v);         \
    FMA2(ZS_, Pe, HAB3v); FMA2(ZS_, Pf, HAB4v);                               \
    float zf_, sp_; UNPACK2(zf_, sp_, ZS_);                                   \
    float s_ = fmaf(THa, hB1, sp_);                                           \
    float h_; TANHA(h_, s_);                                                  \
    float fb_ = fmaf(h_, w2m, MAGICF);                                        \
    unsigned su_ = __reduce_add_sync(FULL, __float_as_uint(fb_));             \
    float af_ = __uint_as_float(su_ + KADJ);                                  \
    float a_ = fmaf(af_, sclv, cbr);                                          \
    TANHA(Snew, a_);                                                          \
    PACKDUP(Pnew, THa);                                                       \
    float z_ = fmaf(THa, hA1, zf_);                                           \
    if (sl) zbuf[ZSL][ZEN][lane] = make_float2(z_, z_);                       \
    float x_ = fmaf(Snew, hM, z_ + hM);                                       \
    if (sl) op[lane] = x_;                                                    \
    op += BATCH * NS;                                                         \
    Q = rqbase[QOFF];                                                         \
} while (0)

#define B_HALF(ZSL, ZEN, EOUT) do {                                           \
    ull a0_ = 0ull, a1_ = 0ull, a2_ = 0ull, a3_ = 0ull;                       \
    const ulonglong2* zq_ = (const ulonglong2*)&zbuf[ZSL][ZEN][0];            \
    _Pragma("unroll")                                                         \
    for (int p_ = 0; p_ < 9; p_++) {                                          \
        ulonglong2 q_ = zq_[p_];                                              \
        if (p_ & 1) { FMA2(a2_, PK[2*p_], q_.x); FMA2(a3_, PK[2*p_+1], q_.y); }\
        else        { FMA2(a0_, PK[2*p_], q_.x); FMA2(a1_, PK[2*p_+1], q_.y); }\
    }                                                                         \
    ull u0_, u1_; ADD2(u0_, a0_, a2_); ADD2(u1_, a1_, a3_); ADD2(EOUT, u0_, u1_); \
} while (0)

#define B_PERIOD(ZSL, ASL) do {                                               \
    ull e0_, e1_;                                                             \
    B_HALF(ZSL, 0, e0_);                                                      \
    B_HALF(ZSL, 1, e1_);                                                      \
    acbuf[ASL][lane] = make_ulonglong2(e0_, e1_);                             \
    BARRIER();                                                                \
} while (0)

__global__ void __launch_bounds__(64, 1)
k_scan(const float* __restrict__ iv, const float* __restrict__ t_eval,
       const float* __restrict__ Tt, float* __restrict__ out)
{
    __shared__ __align__(16) float2 zbuf[2][2][20];
    __shared__ __align__(16) ulonglong2 acbuf[2][32];
    int b = blockIdx.x, tid = threadIdx.x;
    int wid = tid >> 5, lane = tid & 31, hi = lane & 15;
    bool sl = (lane < NS);

    if (wid == 1) {
        // ================= warp B: depth-6 matvec engine =================
        ull PK[NS];
#pragma unroll
        for (int j = 0; j < NS; j++) PK[j] = g_PK[lane * NS + j];
        BARRIER();                                  // pre-loop
        for (int g = 0; g < 8190; g++) {            // 16380 periods
            B_PERIOD(1, 0);                         // even period
            B_PERIOD(0, 1);                         // odd period
        }
        return;
    }

    // ================= warp A: sequential chain =================
    float hA1 = sl ? g_hA[0][lane] : 0.f;
    float hB1 = g_hB[0][hi];
    float hM  = sl ? g_hM[lane] : 0.f;
    float w2m = g_w2m[hi], sclv = g_sclv, cbr = g_cbr;
    ull HAB0, HAB1v, HAB2v, HAB3v, HAB4v;           // d = 2..6
    {
        float a, bb;
        a = sl ? g_hA[1][lane] : 0.f; bb = g_hB[1][hi]; PACK2(HAB0, a, bb);
        a = sl ? g_hA[2][lane] : 0.f; bb = g_hB[2][hi]; PACK2(HAB1v, a, bb);
        a = sl ? g_hA[3][lane] : 0.f; bb = g_hB[3][hi]; PACK2(HAB2v, a, bb);
        a = sl ? g_hA[4][lane] : 0.f; bb = g_hB[4][hi]; PACK2(HAB3v, a, bb);
        a = sl ? g_hA[5][lane] : 0.f; bb = g_hB[5][hi]; PACK2(HAB4v, a, bb);
    }
    float Ph[NS], Gr[NS];
#pragma unroll
    for (int j = 0; j < NS; j++) {
        Ph[j] = sl ? g_Phi[lane * NS + j] : 0.f;
        Gr[j] = g_G[hi * NS + j];
    }
    float P1l = sl ? g_SP[0 * NS + lane] : 0.f;
    float Pml = sl ? g_SP[1 * NS + lane] : 0.f;
    float Pnl = sl ? g_SP[2 * NS + lane] : 0.f;
    float cbl = g_cb[hi], wtowl = g_wtow[hi], wtodl = g_wtod[hi];

    float x = sl ? iv[b * NS + lane] : 0.f;
    if (sl) out[b * NS + lane] = x;                 // row 0 = iv

    // ---- direct steps 0..5 ----
    float zar[6], S[6];
#pragma unroll
    for (int k = 0; k < 6; k++) {
        float ta = Tt[k], tb = Tt[k + 1], tmv = 0.5f * (ta + tb);
        float w = ta * P1l + tmv * Pml + tb * Pnl;
        float tv = t_eval[k];
        float tod = fmodf(tv, 86400.f) * (1.f / 86400.f);
        float tow = fmodf(tv + 259200.f, 604800.f) * (1.f / 604800.f);
        float s = cbl + wtowl * tow + wtodl * tod, z = w;
#pragma unroll
        for (int q = 0; q < NS; q++) {
            float xq = __shfl_sync(FULL, x, q);
            s = fmaf(Gr[q], xq, s);
            z = fmaf(Ph[q], xq, z);
        }
        float th; POLICYM(th, s);
        x = fmaf(th, hM, z + hM);
        if (sl) out[(k + 1) * BATCH * NS + b * NS + lane] = x;
        zar[k] = z; S[k] = th;
    }

    // ---- seeds: AC(z0..z3), zbuf[1] = z4,z5 ----
    ull ACz[4];
#pragma unroll
    for (int i2 = 0; i2 < 4; i2++) {
        ull acc = 0ull;
#pragma unroll
        for (int j = 0; j < NS; j++) {
            ull pk = g_PK[lane * NS + j];
            float zj = __shfl_sync(FULL, zar[i2], j);
            ull zz; PACKDUP(zz, zj);
            FMA2(acc, pk, zz);
        }
        ACz[i2] = acc;
    }
    ulonglong2 ACa = make_ulonglong2(ACz[0], ACz[1]);
    ulonglong2 ACb;
    acbuf[1][lane] = make_ulonglong2(ACz[2], ACz[3]);
    if (sl) {
        zbuf[1][0][lane] = make_float2(zar[4], zar[4]);
        zbuf[1][1][lane] = make_float2(zar[5], zar[5]);
    }

    ull P[6];
#pragma unroll
    for (int i2 = 0; i2 < 6; i2++) PACKDUP(P[i2], S[i2]);

    ull Q0 = g_rec2[6 * 32 + lane], Q1 = g_rec2[7 * 32 + lane];
    ull Q2 = g_rec2[8 * 32 + lane], Q3 = g_rec2[9 * 32 + lane];
    const ull* rqbase = g_rec2 + 10 * 32 + lane;
    float* op = out + 7 * BATCH * NS + b * NS;      // rows 7..

    BARRIER();                                      // pre-loop

    // ---- steady loop: steps 6..32765, 2730 iters x 12 steps ----
    for (int g = 0; g < 2730; g++) {
        ACb = acbuf[1][lane];                       // prefetch for period +1
        STEP_A(S[5], P[4], P[3], P[2], P[1], P[0], S[0], P[0], ACa.x, Q0, 0*32, 0, 0);
        STEP_A(S[0], P[5], P[4], P[3], P[2], P[1], S[1], P[1], ACa.y, Q1, 1*32, 0, 1);
        BARRIER();
        ACa = acbuf[0][lane];
        STEP_A(S[1], P[0], P[5], P[4], P[3], P[2], S[2], P[2], ACb.x, Q2, 2*32, 1, 0);
        STEP_A(S[2], P[1], P[0], P[5], P[4], P[3], S[3], P[3], ACb.y, Q3, 3*32, 1, 1);
        BARRIER();
        ACb = acbuf[1][lane];
        STEP_A(S[3], P[2], P[1], P[0], P[5], P[4], S[4], P[4], ACa.x, Q0, 4*32, 0, 0);
        STEP_A(S[4], P[3], P[2], P[1], P[0], P[5], S[5], P[5], ACa.y, Q1, 5*32, 0, 1);
        BARRIER();
        ACa = acbuf[0][lane];
        STEP_A(S[5], P[4], P[3], P[2], P[1], P[0], S[0], P[0], ACb.x, Q2, 6*32, 1, 0);
        STEP_A(S[0], P[5], P[4], P[3], P[2], P[1], S[1], P[1], ACb.y, Q3, 7*32, 1, 1);
        BARRIER();
        ACb = acbuf[1][lane];
        STEP_A(S[1], P[0], P[5], P[4], P[3], P[2], S[2], P[2], ACa.x, Q0, 8*32, 0, 0);
        STEP_A(S[2], P[1], P[0], P[5], P[4], P[3], S[3], P[3], ACa.y, Q1, 9*32, 0, 1);
        BARRIER();
        ACa = acbuf[0][lane];
        STEP_A(S[3], P[2], P[1], P[0], P[5], P[4], S[4], P[4], ACb.x, Q2, 10*32, 1, 0);
        STEP_A(S[4], P[3], P[2], P[1], P[0], P[5], S[5], P[5], ACb.y, Q3, 11*32, 1, 1);
        BARRIER();
        rqbase += 12 * 32;
    }

    // ---- epilogue: step 32766 (pattern = position 0; AC pair in ACa) ----
    {
        ull ZS_; ADD2(ZS_, ACa.x, Q0);
        FMA2(ZS_, P[4], HAB0); FMA2(ZS_, P[3], HAB1v); FMA2(ZS_, P[2], HAB2v);
        FMA2(ZS_, P[1], HAB3v); FMA2(ZS_, P[0], HAB4v);
        float zf_, sp_; UNPACK2(zf_, sp_, ZS_);
        float s_ = fmaf(S[5], hB1, sp_);
        float th_; POLICYM(th_, s_);
        float z_ = fmaf(S[5], hA1, zf_);
        float x_ = fmaf(th_, hM, z_ + hM);
        if (sl) op[lane] = x_;                      // row 32767
    }
}

// ---------------- launch ------------------------------------------------
extern "C" void kernel_launch(void* const* d_in, const int* in_sizes, int n_in,
                              void* d_out, int out_size)
{
    const float* t_eval = (const float*)d_in[0];
    const float* iv     = (const float*)d_in[1];
    const float* W_A    = (const float*)d_in[2];
    const float* W_B    = (const float*)d_in[3];
    const float* W1     = (const float*)d_in[4];
    const float* b1     = (const float*)d_in[5];
    const float* w2     = (const float*)d_in[6];
    const float* b2     = (const float*)d_in[7];
    const float* Tt     = (const float*)d_in[8];
    float* out = (float*)d_out;

    k_setup<<<1, 576>>>(W_A, W_B, W1, b1, w2, b2);
    k_steps<<<(NSTEP + 7) / 8, 256>>>(t_eval, Tt);
    k_scan<<<BATCH, 64>>>(iv, t_eval, Tt, out);
}

// round 15
// speedup vs baseline: 2.2248x; 1.0342x over previous
#include <cuda_runtime.h>

#define T_STEPS 32768
#define NSTEP   (T_STEPS - 1)    // 32767 RK4 steps; outputs x_1..x_32767
#define BATCH   32
#define NS      18
#define NH      16
#define FULL    0xffffffffu
typedef unsigned long long ull;

// ---------------- device scratch (static, no allocation) ----------------
__device__ float g_Phi[NS * NS];      // Phi fp32 (prologue direct steps)
__device__ float g_G[NH * NS];        // W1[:, :18]/STD (prologue)
__device__ float g_SP[24 * NS];       // state basis: Phi^d P*, d=0..7
__device__ float g_CP[21 * NH];       // policy basis: G Phi^{d-1} P*, d=1..7
__device__ float g_Wc[NS], g_Cc[NH];  // .5*sum_{1..8} Phi^d M / G Phi^{d-1} M
__device__ float g_hA[8][NS];         // .5*Phi^d M, d=1..8  ([d-1])
__device__ float g_hB[8][NH];         // .5*G Phi^{d-1} M, d=1..8
__device__ float g_hM[NS];            // .5*M
__device__ float g_cb[NH], g_wtow[NH], g_wtod[NH];
__device__ float g_w2m[NH];           // w2 * SCL
__device__ float g_sclv, g_cbr;
__device__ ull   g_PK[32 * NS];       // packed rows: lo=Phi8[lane], hi=GPhi7[lane&15]
__device__ ull   g_rec2[(NSTEP + 16) * 32];

// ---------------- packed f32x2 / activation helpers ----------------------
#define FMA2(acc, a, b)  asm("fma.rn.f32x2 %0, %1, %2, %0;" : "+l"(acc) : "l"(a), "l"(b))
#define PACKDUP(d, s)    asm("mov.b64 %0, {%1, %1};" : "=l"(d) : "f"(s))
#define PACK2(d, lo, hi) asm("mov.b64 %0, {%1, %2};" : "=l"(d) : "f"(lo), "f"(hi))
#define UNPACK2(lo, hi, v) asm("mov.b64 {%0, %1}, %2;" : "=f"(lo), "=f"(hi) : "l"(v))
#define ADD2(d, a, b)    asm("add.rn.f32x2 %0, %1, %2;" : "=l"(d) : "l"(a), "l"(b))
#define TANHA(d, s)      asm("tanh.approx.f32 %0, %1;" : "=f"(d) : "f"(s))
#define BARRIER()        asm volatile("bar.sync 0;" ::: "memory")

#define MAGICF 12582912.0f
#define KADJ   (0u - 31u * 0x4B400000u)
#define POLICYM(th_out, s_in) do {                                            \
    float h_; TANHA(h_, (s_in));                                              \
    float fb_ = fmaf(h_, w2m, MAGICF);                                        \
    unsigned su_ = __reduce_add_sync(FULL, __float_as_uint(fb_));             \
    float af_ = __uint_as_float(su_ + KADJ);                                  \
    float a_ = fmaf(af_, sclv, cbr);                                          \
    TANHA((th_out), a_);                                                      \
} while (0)

// ---------------- kernel 0: constants, fp64, 576 threads -----------------
__global__ void __launch_bounds__(576)
k_setup(const float* __restrict__ W_A, const float* __restrict__ W_B,
        const float* __restrict__ W1, const float* __restrict__ b1,
        const float* __restrict__ w2, const float* __restrict__ b2)
{
    __shared__ double A[324], T1[324], T2[324];
    __shared__ double PH[8][324];    // Phi^{d+1}
    __shared__ double GM[8][288];    // G Phi^d
    __shared__ double vt[NS], vr[NS], Md[NS], Pd[3][NS];
    __shared__ double s_scl;
    int t = threadIdx.x;
    int i = t / NS, j = t % NS;

    if (t < 324) A[t] = 1e-4 * (double)W_A[t] - (i == j ? 1e-3 : 0.0);
    if (t < NS) {
        vt[t] = 1e-6 * (double)W_B[t * 17 + 0];
        double s = 0.0;
        for (int c = 1; c < 17; c++) s += (double)W_B[t * 17 + c];
        vr[t] = s * (-16914.0 * 1e-6);
    }
    if (t < 288) GM[0][t] = (double)W1[(t / NS) * 20 + (t % NS)] / 1.41;
    if (t == 0) {
        double ss = 0.0;
        for (int k = 0; k < NH; k++) ss += fabs((double)w2[k]);
        double SCL = exp2(floor(20.0 - log2(ss > 1.0 ? ss : 1.0)));
        s_scl  = SCL;
        g_sclv = (float)(1.0 / (4.0 * SCL));
        g_cbr  = (float)(0.5 * (double)b2[0] - 12582912.0 / (4.0 * SCL));
    }
    __syncthreads();
    if (t < 324) { double s = 0; for (int k = 0; k < NS; k++) s += A[i*NS+k]*A[k*NS+j]; T1[t] = s; }
    __syncthreads();
    if (t < 324) { double s = 0; for (int k = 0; k < NS; k++) s += T1[i*NS+k]*A[k*NS+j]; T2[t] = s; }
    __syncthreads();
    if (t < 324) {
        double a4 = 0; for (int k = 0; k < NS; k++) a4 += T2[i*NS+k]*A[k*NS+j];
        PH[0][t] = (i == j ? 1.0 : 0.0) + 30.0*A[t] + 450.0*T1[t] + 4500.0*T2[t] + 33750.0*a4;
        g_Phi[t] = (float)PH[0][t];
    }
    if (t < NS) {
        double r1=0,r2=0,r3=0,u1=0,u2=0,u3=0;
        for (int k=0;k<NS;k++){ r1+=A[t*NS+k]*vr[k];  u1+=A[t*NS+k]*vt[k]; }
        for (int k=0;k<NS;k++){ r2+=T1[t*NS+k]*vr[k]; u2+=T1[t*NS+k]*vt[k]; }
        for (int k=0;k<NS;k++){ r3+=T2[t*NS+k]*vr[k]; u3+=T2[t*NS+k]*vt[k]; }
        Md[t]    = 30.0*vr[t] + 450.0*r1 + 4500.0*r2 + 33750.0*r3;
        Pd[0][t] =  5.0*vt[t] + 150.0*u1 + 2250.0*u2 + 33750.0*u3;
        Pd[1][t] = 20.0*vt[t] + 300.0*u1 + 2250.0*u2;
        Pd[2][t] =  5.0*vt[t];
        g_hM[t]  = (float)(0.5 * Md[t]);
    }
    __syncthreads();
    for (int d = 1; d < 8; d++) {                  // power chains to Phi^8 / GPhi^7
        if (t < 324) { double s=0; for (int k=0;k<NS;k++) s += PH[d-1][i*NS+k]*PH[0][k*NS+j]; PH[d][t]=s; }
        if (t < 288) { int m=t/NS, jj=t%NS; double s=0; for (int k=0;k<NS;k++) s += GM[d-1][m*NS+k]*PH[0][k*NS+jj]; GM[d][t]=s; }
        __syncthreads();
    }
    if (t < NS) {
        double wc = 0;
        for (int d = 1; d <= 8; d++) {
            double s = 0; for (int k = 0; k < NS; k++) s += PH[d-1][t*NS+k]*Md[k];
            g_hA[d-1][t] = (float)(0.5*s); wc += 0.5*s;
        }
        g_Wc[t] = (float)wc;
        for (int c = 0; c < 3; c++) g_SP[c*NS + t] = (float)Pd[c][t];
        for (int d = 1; d < 8; d++)
            for (int c = 0; c < 3; c++) {
                double s = 0; for (int k = 0; k < NS; k++) s += PH[d-1][t*NS+k]*Pd[c][k];
                g_SP[(3*d+c)*NS + t] = (float)s;
            }
    }
    if (t < NH) {
        double cc = 0;
        for (int d = 1; d <= 8; d++) {
            double s = 0; for (int k = 0; k < NS; k++) s += GM[d-1][t*NS+k]*Md[k];
            g_hB[d-1][t] = (float)(0.5*s); cc += 0.5*s;
        }
        g_Cc[t] = (float)cc;
        for (int d = 1; d <= 7; d++)
            for (int c = 0; c < 3; c++) {
                double s = 0; for (int k = 0; k < NS; k++) s += GM[d-1][t*NS+k]*Pd[c][k];
                g_CP[(3*(d-1)+c)*NH + t] = (float)s;
            }
        double srow = 0; for (int k = 0; k < NS; k++) srow += GM[0][t*NS+k];
        g_cb[t]   = (float)((double)b1[t] - 23.359 * srow);
        g_wtow[t] = W1[t * 20 + 18];
        g_wtod[t] = W1[t * 20 + 19];
        g_w2m[t]  = (float)((double)w2[t] * s_scl);
    }
    if (t < 288) g_G[t] = (float)GM[0][t];
    __syncthreads();
    if (t < 576) {
        int lane = t / NS, jj = t % NS;
        float lo = (lane < NS) ? (float)PH[7][lane*NS+jj] : 0.0f;   // Phi^8
        float hf = (float)GM[7][(lane & 15)*NS+jj];                 // G Phi^7
        g_PK[lane*NS + jj] = ((ull)__float_as_uint(hf) << 32) | (ull)__float_as_uint(lo);
    }
}

// ---------------- kernel 1: per-step packed records (depth-8) ------------
__global__ void k_steps(const float* __restrict__ t_eval, const float* __restrict__ Tt)
{
    int step = blockIdx.x * (blockDim.x >> 5) + (threadIdx.x >> 5);
    int lane = threadIdx.x & 31;
    if (step >= NSTEP) return;

    float t1[8], tm[8], tn[8];
#pragma unroll
    for (int d = 0; d < 8; d++) {
        int kk = step - d; if (kk < 0) kk = 0;
        t1[d] = Tt[kk]; tn[d] = Tt[kk + 1]; tm[d] = 0.5f * (t1[d] + tn[d]);
    }
    float t   = t_eval[step];
    float tod = fmodf(t, 86400.f) * (1.f / 86400.f);
    float tow = fmodf(t + 259200.f, 604800.f) * (1.f / 604800.f);

    float Wl = 0.f;
    if (lane < NS) {
        Wl = g_Wc[lane];
#pragma unroll
        for (int d = 0; d < 8; d++)
            Wl += t1[d] * g_SP[(3*d+0)*NS + lane] + tm[d] * g_SP[(3*d+1)*NS + lane]
                + tn[d] * g_SP[(3*d+2)*NS + lane];
    }
    int hi = lane & 15;
    float Cl = g_cb[hi] + g_wtow[hi] * tow + g_wtod[hi] * tod + g_Cc[hi];
#pragma unroll
    for (int d = 1; d <= 7; d++)
        Cl += t1[d] * g_CP[(3*(d-1)+0)*NH + hi] + tm[d] * g_CP[(3*(d-1)+1)*NH + hi]
            + tn[d] * g_CP[(3*(d-1)+2)*NH + hi];

    g_rec2[step * 32 + lane] = ((ull)__float_as_uint(Cl) << 32) | (ull)__float_as_uint(Wl);
}

// ---------------- kernel 2: warp-specialized scan, 3 warps ----------------
// A (warp0): th chain only, 1 bar per 4-step quad.
// B1 (warp1): AC matvec of quad z-entries 0,1;  B2 (warp2): entries 2,3.
// Pipeline lag 8: z (quad q) -> AC (quad q+1) -> consumed (quad q+2).
#define STEP_A(THa, PA, PB, PC, PD_, PE, PF, PG, Snew, Pnew, ACreg, Q, QOFF, ZSL, ZEN) do { \
    ull ZS_; ADD2(ZS_, ACreg, Q);                                             \
    FMA2(ZS_, PA, HB2); FMA2(ZS_, PB, HB3); FMA2(ZS_, PC, HB4);               \
    FMA2(ZS_, PD_, HB5); FMA2(ZS_, PE, HB6); FMA2(ZS_, PF, HB7);              \
    FMA2(ZS_, PG, HB8);                                                       \
    float zf_, sp_; UNPACK2(zf_, sp_, ZS_);                                   \
    float s_ = fmaf(THa, hB1, sp_);                                           \
    float h_; TANHA(h_, s_);                                                  \
    float fb_ = fmaf(h_, w2m, MAGICF);                                        \
    unsigned su_ = __reduce_add_sync(FULL, __float_as_uint(fb_));             \
    float af_ = __uint_as_float(su_ + KADJ);                                  \
    float a_ = fmaf(af_, sclv, cbr);                                          \
    TANHA(Snew, a_);                                                          \
    PACKDUP(Pnew, THa);                                                       \
    float z_ = fmaf(THa, hA1, zf_);                                           \
    if (sl) zbuf[ZSL][ZEN][lane] = make_float2(z_, z_);                       \
    float x_ = fmaf(Snew, hM, z_ + hM);                                       \
    if (sl) op[lane] = x_;                                                    \
    op += BATCH * NS;                                                         \
    Q = rqbase[QOFF];                                                         \
} while (0)

#define B_MAT(ZP, EOUT) do {                                                  \
    ull a0_ = 0ull, a1_ = 0ull, a2_ = 0ull, a3_ = 0ull;                       \
    const ulonglong2* zq_ = (const ulonglong2*)(ZP);                          \
    _Pragma("unroll")                                                         \
    for (int p_ = 0; p_ < 9; p_++) {                                          \
        ulonglong2 q_ = zq_[p_];                                              \
        if (p_ & 1) { FMA2(a2_, PK[2*p_], q_.x); FMA2(a3_, PK[2*p_+1], q_.y); }\
        else        { FMA2(a0_, PK[2*p_], q_.x); FMA2(a1_, PK[2*p_+1], q_.y); }\
    }                                                                         \
    ull u0_, u1_; ADD2(u0_, a0_, a2_); ADD2(u1_, a1_, a3_); ADD2(EOUT, u0_, u1_); \
} while (0)

__global__ void __launch_bounds__(96, 1)
k_scan(const float* __restrict__ iv, const float* __restrict__ t_eval,
       const float* __restrict__ Tt, float* __restrict__ out)
{
    __shared__ __align__(16) float2 zbuf[2][4][20];
    __shared__ __align__(16) ulonglong2 acbuf[2][2][32];
    int b = blockIdx.x, tid = threadIdx.x;
    int wid = tid >> 5, lane = tid & 31, hi = lane & 15;
    bool sl = (lane < NS);

    if (wid >= 1) {
        // ============ warps B1/B2: AC matvec engines ============
        ull PK[NS];
#pragma unroll
        for (int j = 0; j < NS; j++) PK[j] = g_PK[lane * NS + j];
        int bi = wid - 1;                 // 0: entries 0,1   1: entries 2,3
        BARRIER();                                    // pre-loop
        for (int g = 0; g < 4094; g++) {
            { ull e0, e1;                             // quad even: z from slot 1
              B_MAT(&zbuf[1][2*bi][0], e0);
              B_MAT(&zbuf[1][2*bi+1][0], e1);
              acbuf[1][bi][lane] = make_ulonglong2(e0, e1); }
            BARRIER();
            { ull e0, e1;                             // quad odd: z from slot 0
              B_MAT(&zbuf[0][2*bi][0], e0);
              B_MAT(&zbuf[0][2*bi+1][0], e1);
              acbuf[0][bi][lane] = make_ulonglong2(e0, e1); }
            BARRIER();
        }
        return;
    }

    // ================= warp A: sequential chain =================
    float hA1 = sl ? g_hA[0][lane] : 0.f;
    float hB1 = g_hB[0][hi];
    float hM  = sl ? g_hM[lane] : 0.f;
    float w2m = g_w2m[hi], sclv = g_sclv, cbr = g_cbr;
    ull HB2, HB3, HB4, HB5, HB6, HB7, HB8;           // packed (.5 Phi^d M, .5 G Phi^{d-1} M), d=2..8
    {
        float a, bb;
        a = sl ? g_hA[1][lane] : 0.f; bb = g_hB[1][hi]; PACK2(HB2, a, bb);
        a = sl ? g_hA[2][lane] : 0.f; bb = g_hB[2][hi]; PACK2(HB3, a, bb);
        a = sl ? g_hA[3][lane] : 0.f; bb = g_hB[3][hi]; PACK2(HB4, a, bb);
        a = sl ? g_hA[4][lane] : 0.f; bb = g_hB[4][hi]; PACK2(HB5, a, bb);
        a = sl ? g_hA[5][lane] : 0.f; bb = g_hB[5][hi]; PACK2(HB6, a, bb);
        a = sl ? g_hA[6][lane] : 0.f; bb = g_hB[6][hi]; PACK2(HB7, a, bb);
        a = sl ? g_hA[7][lane] : 0.f; bb = g_hB[7][hi]; PACK2(HB8, a, bb);
    }
    float Ph[NS], Gr[NS];
#pragma unroll
    for (int j = 0; j < NS; j++) {
        Ph[j] = sl ? g_Phi[lane * NS + j] : 0.f;
        Gr[j] = g_G[hi * NS + j];
    }
    float P1l = sl ? g_SP[0 * NS + lane] : 0.f;
    float Pml = sl ? g_SP[1 * NS + lane] : 0.f;
    float Pnl = sl ? g_SP[2 * NS + lane] : 0.f;
    float cbl = g_cb[hi], wtowl = g_wtow[hi], wtodl = g_wtod[hi];

    float x = sl ? iv[b * NS + lane] : 0.f;
    if (sl) out[b * NS + lane] = x;                  // row 0 = iv

    // ---- direct steps 0..14 (shuffle matvec) ----
    float zar[15], tha[15];
#pragma unroll
    for (int k = 0; k < 15; k++) {
        float ta = Tt[k], tb = Tt[k + 1], tmv = 0.5f * (ta + tb);
        float w = ta * P1l + tmv * Pml + tb * Pnl;
        float tv = t_eval[k];
        float tod = fmodf(tv, 86400.f) * (1.f / 86400.f);
        float tow = fmodf(tv + 259200.f, 604800.f) * (1.f / 604800.f);
        float s = cbl + wtowl * tow + wtodl * tod, z = w;
#pragma unroll
        for (int q = 0; q < NS; q++) {
            float xq = __shfl_sync(FULL, x, q);
            s = fmaf(Gr[q], xq, s);
            z = fmaf(Ph[q], xq, z);
        }
        float th; POLICYM(th, s);
        x = fmaf(th, hM, z + hM);
        if (sl) out[(k + 1) * BATCH * NS + b * NS + lane] = x;
        zar[k] = z; tha[k] = th;
    }

    // ---- seeds: acbuf[0] = AC(z7..z10); zbuf[1] = z11..z14 ----
    {
        ull ACz[4];
#pragma unroll
        for (int i2 = 0; i2 < 4; i2++) {
            ull acc = 0ull;
#pragma unroll
            for (int j = 0; j < NS; j++) {
                ull pk = g_PK[lane * NS + j];
                float zj = __shfl_sync(FULL, zar[7 + i2], j);
                ull zz; PACKDUP(zz, zj);
                FMA2(acc, pk, zz);
            }
            ACz[i2] = acc;
        }
        acbuf[0][0][lane] = make_ulonglong2(ACz[0], ACz[1]);
        acbuf[0][1][lane] = make_ulonglong2(ACz[2], ACz[3]);
        if (sl) {
            zbuf[1][0][lane] = make_float2(zar[11], zar[11]);
            zbuf[1][1][lane] = make_float2(zar[12], zar[12]);
            zbuf[1][2][lane] = make_float2(zar[13], zar[13]);
            zbuf[1][3][lane] = make_float2(zar[14], zar[14]);
        }
    }

    // th rings: S[i] = th_{7+i} (scalar), P[i] = packed th_{6+i}
    float S0 = tha[7], S1 = tha[8], S2 = tha[9],  S3 = tha[10];
    float S4 = tha[11], S5 = tha[12], S6 = tha[13], S7 = tha[14];
    ull P0, P1, P2, P3, P4, P5, P6, P7;
    PACKDUP(P0, tha[6]);  PACKDUP(P1, tha[7]);  PACKDUP(P2, tha[8]);
    PACKDUP(P3, tha[9]);  PACKDUP(P4, tha[10]); PACKDUP(P5, tha[11]);
    PACKDUP(P6, tha[12]); PACKDUP(P7, tha[13]);

    ull Q0 = g_rec2[15*32 + lane], Q1 = g_rec2[16*32 + lane];
    ull Q2 = g_rec2[17*32 + lane], Q3 = g_rec2[18*32 + lane];
    ull Q4 = g_rec2[19*32 + lane], Q5 = g_rec2[20*32 + lane];
    ull Q6 = g_rec2[21*32 + lane], Q7 = g_rec2[22*32 + lane];
    const ull* rqbase = g_rec2 + 23 * 32 + lane;
    float* op = out + 16 * BATCH * NS + b * NS;      // rows 16..32767

    BARRIER();                                       // pre-loop

    // ---- steady loop: steps 15..32766 = 32752 = 8 * 4094 ----
    for (int g = 0; g < 4094; g++) {
        ulonglong2 ACa = acbuf[0][0][lane];
        ulonglong2 ACb = acbuf[0][1][lane];
        STEP_A(S7, P7, P6, P5, P4, P3, P2, P1, S0, P0, ACa.x, Q0, 0*32, 0, 0);
        STEP_A(S0, P0, P7, P6, P5, P4, P3, P2, S1, P1, ACa.y, Q1, 1*32, 0, 1);
        STEP_A(S1, P1, P0, P7, P6, P5, P4, P3, S2, P2, ACb.x, Q2, 2*32, 0, 2);
        STEP_A(S2, P2, P1, P0, P7, P6, P5, P4, S3, P3, ACb.y, Q3, 3*32, 0, 3);
        BARRIER();
        ACa = acbuf[1][0][lane];
        ACb = acbuf[1][1][lane];
        STEP_A(S3, P3, P2, P1, P0, P7, P6, P5, S4, P4, ACa.x, Q4, 4*32, 1, 0);
        STEP_A(S4, P4, P3, P2, P1, P0, P7, P6, S5, P5, ACa.y, Q5, 5*32, 1, 1);
        STEP_A(S5, P5, P4, P3, P2, P1, P0, P7, S6, P6, ACb.x, Q6, 6*32, 1, 2);
        STEP_A(S6, P6, P5, P4, P3, P2, P1, P0, S7, P7, ACb.y, Q7, 7*32, 1, 3);
        BARRIER();
        rqbase += 8 * 32;
    }
}

// ---------------- launch ------------------------------------------------
extern "C" void kernel_launch(void* const* d_in, const int* in_sizes, int n_in,
                              void* d_out, int out_size)
{
    const float* t_eval = (const float*)d_in[0];
    const float* iv     = (const float*)d_in[1];
    const float* W_A    = (const float*)d_in[2];
    const float* W_B    = (const float*)d_in[3];
    const float* W1     = (const float*)d_in[4];
    const float* b1     = (const float*)d_in[5];
    const float* w2     = (const float*)d_in[6];
    const float* b2     = (const float*)d_in[7];
    const float* Tt     = (const float*)d_in[8];
    float* out = (float*)d_out;

    k_setup<<<1, 576>>>(W_A, W_B, W1, b1, w2, b2);
    k_steps<<<(NSTEP + 7) / 8, 256>>>(t_eval, Tt);
    k_scan<<<BATCH, 96>>>(iv, t_eval, Tt, out);
}

// round 16
// speedup vs baseline: 2.2274x; 1.0012x over previous
#include <cuda_runtime.h>

#define T_STEPS 32768
#define NSTEP   (T_STEPS - 1)    // 32767 RK4 steps; outputs x_1..x_32767
#define BATCH   32
#define NS      18
#define NH      16
#define FULL    0xffffffffu
typedef unsigned long long ull;

// ---------------- device scratch (static, no allocation) ----------------
__device__ float g_Phi[NS * NS];      // Phi fp32 (prologue direct steps)
__device__ float g_G[NH * NS];        // W1[:, :18]/STD (prologue)
__device__ float g_SP[24 * NS];       // state basis: Phi^d P*, d=0..7
__device__ float g_CP[21 * NH];       // policy basis: G Phi^{d-1} P*, d=1..7
__device__ float g_Wc[NS], g_Cc[NH];  // .5*sum_{1..8} Phi^d M / G Phi^{d-1} M
__device__ float g_hA[8][NS];         // .5*Phi^d M, d=1..8  ([d-1])
__device__ float g_hB[8][NH];         // .5*G Phi^{d-1} M, d=1..8
__device__ float g_hM[NS];            // .5*M
__device__ float g_cb[NH], g_wtow[NH], g_wtod[NH];
__device__ float g_w2m[NH];           // w2 * SCL
__device__ float g_sclv, g_cbr;
__device__ ull   g_PK[32 * NS];       // packed rows: lo=Phi8[lane], hi=GPhi7[lane&15]
__device__ ull   g_rec2[(NSTEP + 16) * 32];

// ---------------- packed f32x2 / activation helpers ----------------------
#define FMA2(acc, a, b)  asm("fma.rn.f32x2 %0, %1, %2, %0;" : "+l"(acc) : "l"(a), "l"(b))
#define PACKDUP(d, s)    asm("mov.b64 %0, {%1, %1};" : "=l"(d) : "f"(s))
#define PACK2(d, lo, hi) asm("mov.b64 %0, {%1, %2};" : "=l"(d) : "f"(lo), "f"(hi))
#define UNPACK2(lo, hi, v) asm("mov.b64 {%0, %1}, %2;" : "=f"(lo), "=f"(hi) : "l"(v))
#define ADD2(d, a, b)    asm("add.rn.f32x2 %0, %1, %2;" : "=l"(d) : "l"(a), "l"(b))
#define TANHA(d, s)      asm("tanh.approx.f32 %0, %1;" : "=f"(d) : "f"(s))
#define BARRIER()        asm volatile("bar.sync 0;" ::: "memory")

#define MAGICF 12582912.0f
#define KADJ   (0u - 31u * 0x4B400000u)
#define POLICYM(th_out, s_in) do {                                            \
    float h_; TANHA(h_, (s_in));                                              \
    float fb_ = fmaf(h_, w2m, MAGICF);                                        \
    unsigned su_ = __reduce_add_sync(FULL, __float_as_uint(fb_));             \
    float af_ = __uint_as_float(su_ + KADJ);                                  \
    float a_ = fmaf(af_, sclv, cbr);                                          \
    TANHA((th_out), a_);                                                      \
} while (0)

// ---------------- kernel 0: constants, fp64, 576 threads -----------------
__global__ void __launch_bounds__(576)
k_setup(const float* __restrict__ W_A, const float* __restrict__ W_B,
        const float* __restrict__ W1, const float* __restrict__ b1,
        const float* __restrict__ w2, const float* __restrict__ b2)
{
    __shared__ double A[324], T1[324], T2[324];
    __shared__ double PH[8][324];    // Phi^{d+1}
    __shared__ double GM[8][288];    // G Phi^d
    __shared__ double vt[NS], vr[NS], Md[NS], Pd[3][NS];
    __shared__ double s_scl;
    int t = threadIdx.x;
    int i = t / NS, j = t % NS;

    if (t < 324) A[t] = 1e-4 * (double)W_A[t] - (i == j ? 1e-3 : 0.0);
    if (t < NS) {
        vt[t] = 1e-6 * (double)W_B[t * 17 + 0];
        double s = 0.0;
        for (int c = 1; c < 17; c++) s += (double)W_B[t * 17 + c];
        vr[t] = s * (-16914.0 * 1e-6);
    }
    if (t < 288) GM[0][t] = (double)W1[(t / NS) * 20 + (t % NS)] / 1.41;
    if (t == 0) {
        double ss = 0.0;
        for (int k = 0; k < NH; k++) ss += fabs((double)w2[k]);
        double SCL = exp2(floor(20.0 - log2(ss > 1.0 ? ss : 1.0)));
        s_scl  = SCL;
        g_sclv = (float)(1.0 / (4.0 * SCL));
        g_cbr  = (float)(0.5 * (double)b2[0] - 12582912.0 / (4.0 * SCL));
    }
    __syncthreads();
    if (t < 324) { double s = 0; for (int k = 0; k < NS; k++) s += A[i*NS+k]*A[k*NS+j]; T1[t] = s; }
    __syncthreads();
    if (t < 324) { double s = 0; for (int k = 0; k < NS; k++) s += T1[i*NS+k]*A[k*NS+j]; T2[t] = s; }
    __syncthreads();
    if (t < 324) {
        double a4 = 0; for (int k = 0; k < NS; k++) a4 += T2[i*NS+k]*A[k*NS+j];
        PH[0][t] = (i == j ? 1.0 : 0.0) + 30.0*A[t] + 450.0*T1[t] + 4500.0*T2[t] + 33750.0*a4;
        g_Phi[t] = (float)PH[0][t];
    }
    if (t < NS) {
        double r1=0,r2=0,r3=0,u1=0,u2=0,u3=0;
        for (int k=0;k<NS;k++){ r1+=A[t*NS+k]*vr[k];  u1+=A[t*NS+k]*vt[k]; }
        for (int k=0;k<NS;k++){ r2+=T1[t*NS+k]*vr[k]; u2+=T1[t*NS+k]*vt[k]; }
        for (int k=0;k<NS;k++){ r3+=T2[t*NS+k]*vr[k]; u3+=T2[t*NS+k]*vt[k]; }
        Md[t]    = 30.0*vr[t] + 450.0*r1 + 4500.0*r2 + 33750.0*r3;
        Pd[0][t] =  5.0*vt[t] + 150.0*u1 + 2250.0*u2 + 33750.0*u3;
        Pd[1][t] = 20.0*vt[t] + 300.0*u1 + 2250.0*u2;
        Pd[2][t] =  5.0*vt[t];
        g_hM[t]  = (float)(0.5 * Md[t]);
    }
    __syncthreads();
    for (int d = 1; d < 8; d++) {                  // power chains to Phi^8 / GPhi^7
        if (t < 324) { double s=0; for (int k=0;k<NS;k++) s += PH[d-1][i*NS+k]*PH[0][k*NS+j]; PH[d][t]=s; }
        if (t < 288) { int m=t/NS, jj=t%NS; double s=0; for (int k=0;k<NS;k++) s += GM[d-1][m*NS+k]*PH[0][k*NS+jj]; GM[d][t]=s; }
        __syncthreads();
    }
    if (t < NS) {
        double wc = 0;
        for (int d = 1; d <= 8; d++) {
            double s = 0; for (int k = 0; k < NS; k++) s += PH[d-1][t*NS+k]*Md[k];
            g_hA[d-1][t] = (float)(0.5*s); wc += 0.5*s;
        }
        g_Wc[t] = (float)wc;
        for (int c = 0; c < 3; c++) g_SP[c*NS + t] = (float)Pd[c][t];
        for (int d = 1; d < 8; d++)
            for (int c = 0; c < 3; c++) {
                double s = 0; for (int k = 0; k < NS; k++) s += PH[d-1][t*NS+k]*Pd[c][k];
                g_SP[(3*d+c)*NS + t] = (float)s;
            }
    }
    if (t < NH) {
        double cc = 0;
        for (int d = 1; d <= 8; d++) {
            double s = 0; for (int k = 0; k < NS; k++) s += GM[d-1][t*NS+k]*Md[k];
            g_hB[d-1][t] = (float)(0.5*s); cc += 0.5*s;
        }
        g_Cc[t] = (float)cc;
        for (int d = 1; d <= 7; d++)
            for (int c = 0; c < 3; c++) {
                double s = 0; for (int k = 0; k < NS; k++) s += GM[d-1][t*NS+k]*Pd[c][k];
                g_CP[(3*(d-1)+c)*NH + t] = (float)s;
            }
        double srow = 0; for (int k = 0; k < NS; k++) srow += GM[0][t*NS+k];
        g_cb[t]   = (float)((double)b1[t] - 23.359 * srow);
        g_wtow[t] = W1[t * 20 + 18];
        g_wtod[t] = W1[t * 20 + 19];
        g_w2m[t]  = (float)((double)w2[t] * s_scl);
    }
    if (t < 288) g_G[t] = (float)GM[0][t];
    __syncthreads();
    if (t < 576) {
        int lane = t / NS, jj = t % NS;
        float lo = (lane < NS) ? (float)PH[7][lane*NS+jj] : 0.0f;   // Phi^8
        float hf = (float)GM[7][(lane & 15)*NS+jj];                 // G Phi^7
        g_PK[lane*NS + jj] = ((ull)__float_as_uint(hf) << 32) | (ull)__float_as_uint(lo);
    }
}

// ---------------- kernel 1: per-step packed records (depth-8) ------------
__global__ void k_steps(const float* __restrict__ t_eval, const float* __restrict__ Tt)
{
    int step = blockIdx.x * (blockDim.x >> 5) + (threadIdx.x >> 5);
    int lane = threadIdx.x & 31;
    if (step >= NSTEP) return;

    float t1[8], tm[8], tn[8];
#pragma unroll
    for (int d = 0; d < 8; d++) {
        int kk = step - d; if (kk < 0) kk = 0;
        t1[d] = Tt[kk]; tn[d] = Tt[kk + 1]; tm[d] = 0.5f * (t1[d] + tn[d]);
    }
    float t   = t_eval[step];
    float tod = fmodf(t, 86400.f) * (1.f / 86400.f);
    float tow = fmodf(t + 259200.f, 604800.f) * (1.f / 604800.f);

    float Wl = 0.f;
    if (lane < NS) {
        Wl = g_Wc[lane];
#pragma unroll
        for (int d = 0; d < 8; d++)
            Wl += t1[d] * g_SP[(3*d+0)*NS + lane] + tm[d] * g_SP[(3*d+1)*NS + lane]
                + tn[d] * g_SP[(3*d+2)*NS + lane];
    }
    int hi = lane & 15;
    float Cl = g_cb[hi] + g_wtow[hi] * tow + g_wtod[hi] * tod + g_Cc[hi];
#pragma unroll
    for (int d = 1; d <= 7; d++)
        Cl += t1[d] * g_CP[(3*(d-1)+0)*NH + hi] + tm[d] * g_CP[(3*(d-1)+1)*NH + hi]
            + tn[d] * g_CP[(3*(d-1)+2)*NH + hi];

    g_rec2[step * 32 + lane] = ((ull)__float_as_uint(Cl) << 32) | (ull)__float_as_uint(Wl);
}

// ---------------- kernel 2: warp-specialized scan, 3 warps ----------------
// A (warp0): th chain only, 1 bar per 4-step quad.
// B1 (warp1): AC matvec of quad z-entries 0,1;  B2 (warp2): entries 2,3.
// Pipeline lag 8: z (quad q) -> AC (quad q+1) -> consumed (quad q+2).
#define STEP_A(THa, PA, PB, PC, PD_, PE, PF, PG, Snew, Pnew, ACreg, Q, QOFF, ZSL, ZEN) do { \
    ull ZS_; ADD2(ZS_, ACreg, Q);                                             \
    FMA2(ZS_, PA, HB2); FMA2(ZS_, PB, HB3); FMA2(ZS_, PC, HB4);               \
    FMA2(ZS_, PD_, HB5); FMA2(ZS_, PE, HB6); FMA2(ZS_, PF, HB7);              \
    FMA2(ZS_, PG, HB8);                                                       \
    float zf_, sp_; UNPACK2(zf_, sp_, ZS_);                                   \
    float s_ = fmaf(THa, hB1, sp_);                                           \
    float h_; TANHA(h_, s_);                                                  \
    float fb_ = fmaf(h_, w2m, MAGICF);                                        \
    unsigned su_ = __reduce_add_sync(FULL, __float_as_uint(fb_));             \
    float af_ = __uint_as_float(su_ + KADJ);                                  \
    float a_ = fmaf(af_, sclv, cbr);                                          \
    TANHA(Snew, a_);                                                          \
    PACKDUP(Pnew, THa);                                                       \
    float z_ = fmaf(THa, hA1, zf_);                                           \
    if (sl) zbuf[ZSL][ZEN][lane] = make_float2(z_, z_);                       \
    float x_ = fmaf(Snew, hM, z_ + hM);                                       \
    if (sl) op[lane] = x_;                                                    \
    op += BATCH * NS;                                                         \
    Q = rqbase[QOFF];                                                         \
} while (0)

#define B_MAT(ZP, EOUT) do {                                                  \
    ull a0_ = 0ull, a1_ = 0ull, a2_ = 0ull, a3_ = 0ull;                       \
    const ulonglong2* zq_ = (const ulonglong2*)(ZP);                          \
    _Pragma("unroll")                                                         \
    for (int p_ = 0; p_ < 9; p_++) {                                          \
        ulonglong2 q_ = zq_[p_];                                              \
        if (p_ & 1) { FMA2(a2_, PK[2*p_], q_.x); FMA2(a3_, PK[2*p_+1], q_.y); }\
        else        { FMA2(a0_, PK[2*p_], q_.x); FMA2(a1_, PK[2*p_+1], q_.y); }\
    }                                                                         \
    ull u0_, u1_; ADD2(u0_, a0_, a2_); ADD2(u1_, a1_, a3_); ADD2(EOUT, u0_, u1_); \
} while (0)

__global__ void __launch_bounds__(96, 1)
k_scan(const float* __restrict__ iv, const float* __restrict__ t_eval,
       const float* __restrict__ Tt, float* __restrict__ out)
{
    __shared__ __align__(16) float2 zbuf[2][4][20];
    __shared__ __align__(16) ulonglong2 acbuf[2][2][32];
    int b = blockIdx.x, tid = threadIdx.x;
    int wid = tid >> 5, lane = tid & 31, hi = lane & 15;
    bool sl = (lane < NS);

    if (wid >= 1) {
        // ============ warps B1/B2: AC matvec engines ============
        ull PK[NS];
#pragma unroll
        for (int j = 0; j < NS; j++) PK[j] = g_PK[lane * NS + j];
        int bi = wid - 1;                 // 0: entries 0,1   1: entries 2,3
        BARRIER();                                    // pre-loop
        for (int g = 0; g < 4094; g++) {
            { ull e0, e1;                             // quad even: z from slot 1
              B_MAT(&zbuf[1][2*bi][0], e0);
              B_MAT(&zbuf[1][2*bi+1][0], e1);
              acbuf[1][bi][lane] = make_ulonglong2(e0, e1); }
            BARRIER();
            { ull e0, e1;                             // quad odd: z from slot 0
              B_MAT(&zbuf[0][2*bi][0], e0);
              B_MAT(&zbuf[0][2*bi+1][0], e1);
              acbuf[0][bi][lane] = make_ulonglong2(e0, e1); }
            BARRIER();
        }
        return;
    }

    // ================= warp A: sequential chain =================
    float hA1 = sl ? g_hA[0][lane] : 0.f;
    float hB1 = g_hB[0][hi];
    float hM  = sl ? g_hM[lane] : 0.f;
    float w2m = g_w2m[hi], sclv = g_sclv, cbr = g_cbr;
    ull HB2, HB3, HB4, HB5, HB6, HB7, HB8;           // packed (.5 Phi^d M, .5 G Phi^{d-1} M), d=2..8
    {
        float a, bb;
        a = sl ? g_hA[1][lane] : 0.f; bb = g_hB[1][hi]; PACK2(HB2, a, bb);
        a = sl ? g_hA[2][lane] : 0.f; bb = g_hB[2][hi]; PACK2(HB3, a, bb);
        a = sl ? g_hA[3][lane] : 0.f; bb = g_hB[3][hi]; PACK2(HB4, a, bb);
        a = sl ? g_hA[4][lane] : 0.f; bb = g_hB[4][hi]; PACK2(HB5, a, bb);
        a = sl ? g_hA[5][lane] : 0.f; bb = g_hB[5][hi]; PACK2(HB6, a, bb);
        a = sl ? g_hA[6][lane] : 0.f; bb = g_hB[6][hi]; PACK2(HB7, a, bb);
        a = sl ? g_hA[7][lane] : 0.f; bb = g_hB[7][hi]; PACK2(HB8, a, bb);
    }
    float Ph[NS], Gr[NS];
#pragma unroll
    for (int j = 0; j < NS; j++) {
        Ph[j] = sl ? g_Phi[lane * NS + j] : 0.f;
        Gr[j] = g_G[hi * NS + j];
    }
    float P1l = sl ? g_SP[0 * NS + lane] : 0.f;
    float Pml = sl ? g_SP[1 * NS + lane] : 0.f;
    float Pnl = sl ? g_SP[2 * NS + lane] : 0.f;
    float cbl = g_cb[hi], wtowl = g_wtow[hi], wtodl = g_wtod[hi];

    float x = sl ? iv[b * NS + lane] : 0.f;
    if (sl) out[b * NS + lane] = x;                  // row 0 = iv

    // ---- direct steps 0..14 (shuffle matvec) ----
    float zar[15], tha[15];
#pragma unroll
    for (int k = 0; k < 15; k++) {
        float ta = Tt[k], tb = Tt[k + 1], tmv = 0.5f * (ta + tb);
        float w = ta * P1l + tmv * Pml + tb * Pnl;
        float tv = t_eval[k];
        float tod = fmodf(tv, 86400.f) * (1.f / 86400.f);
        float tow = fmodf(tv + 259200.f, 604800.f) * (1.f / 604800.f);
        float s = cbl + wtowl * tow + wtodl * tod, z = w;
#pragma unroll
        for (int q = 0; q < NS; q++) {
            float xq = __shfl_sync(FULL, x, q);
            s = fmaf(Gr[q], xq, s);
            z = fmaf(Ph[q], xq, z);
        }
        float th; POLICYM(th, s);
        x = fmaf(th, hM, z + hM);
        if (sl) out[(k + 1) * BATCH * NS + b * NS + lane] = x;
        zar[k] = z; tha[k] = th;
    }

    // ---- seeds: acbuf[0] = AC(z7..z10); zbuf[1] = z11..z14 ----
    {
        ull ACz[4];
#pragma unroll
        for (int i2 = 0; i2 < 4; i2++) {
            ull acc = 0ull;
#pragma unroll
            for (int j = 0; j < NS; j++) {
                ull pk = g_PK[lane * NS + j];
                float zj = __shfl_sync(FULL, zar[7 + i2], j);
                ull zz; PACKDUP(zz, zj);
                FMA2(acc, pk, zz);
            }
            ACz[i2] = acc;
        }
        acbuf[0][0][lane] = make_ulonglong2(ACz[0], ACz[1]);
        acbuf[0][1][lane] = make_ulonglong2(ACz[2], ACz[3]);
        if (sl) {
            zbuf[1][0][lane] = make_float2(zar[11], zar[11]);
            zbuf[1][1][lane] = make_float2(zar[12], zar[12]);
            zbuf[1][2][lane] = make_float2(zar[13], zar[13]);
            zbuf[1][3][lane] = make_float2(zar[14], zar[14]);
        }
    }

    // th rings: S[i] = th_{7+i} (scalar), P[i] = packed th_{6+i}
    float S0 = tha[7], S1 = tha[8], S2 = tha[9],  S3 = tha[10];
    float S4 = tha[11], S5 = tha[12], S6 = tha[13], S7 = tha[14];
    ull P0, P1, P2, P3, P4, P5, P6, P7;
    PACKDUP(P0, tha[6]);  PACKDUP(P1, tha[7]);  PACKDUP(P2, tha[8]);
    PACKDUP(P3, tha[9]);  PACKDUP(P4, tha[10]); PACKDUP(P5, tha[11]);
    PACKDUP(P6, tha[12]); PACKDUP(P7, tha[13]);

    ull Q0 = g_rec2[15*32 + lane], Q1 = g_rec2[16*32 + lane];
    ull Q2 = g_rec2[17*32 + lane], Q3 = g_rec2[18*32 + lane];
    ull Q4 = g_rec2[19*32 + lane], Q5 = g_rec2[20*32 + lane];
    ull Q6 = g_rec2[21*32 + lane], Q7 = g_rec2[22*32 + lane];
    const ull* rqbase = g_rec2 + 23 * 32 + lane;
    float* op = out + 16 * BATCH * NS + b * NS;      // rows 16..32767

    BARRIER();                                       // pre-loop

    // ---- steady loop: steps 15..32766 = 32752 = 8 * 4094 ----
    for (int g = 0; g < 4094; g++) {
        ulonglong2 ACa = acbuf[0][0][lane];
        ulonglong2 ACb = acbuf[0][1][lane];
        STEP_A(S7, P7, P6, P5, P4, P3, P2, P1, S0, P0, ACa.x, Q0, 0*32, 0, 0);
        STEP_A(S0, P0, P7, P6, P5, P4, P3, P2, S1, P1, ACa.y, Q1, 1*32, 0, 1);
        STEP_A(S1, P1, P0, P7, P6, P5, P4, P3, S2, P2, ACb.x, Q2, 2*32, 0, 2);
        STEP_A(S2, P2, P1, P0, P7, P6, P5, P4, S3, P3, ACb.y, Q3, 3*32, 0, 3);
        BARRIER();
        ACa = acbuf[1][0][lane];
        ACb = acbuf[1][1][lane];
        STEP_A(S3, P3, P2, P1, P0, P7, P6, P5, S4, P4, ACa.x, Q4, 4*32, 1, 0);
        STEP_A(S4, P4, P3, P2, P1, P0, P7, P6, S5, P5, ACa.y, Q5, 5*32, 1, 1);
        STEP_A(S5, P5, P4, P3, P2, P1, P0, P7, S6, P6, ACb.x, Q6, 6*32, 1, 2);
        STEP_A(S6, P6, P5, P4, P3, P2, P1, P0, S7, P7, ACb.y, Q7, 7*32, 1, 3);
        BARRIER();
        rqbase += 8 * 32;
    }
}

// ---------------- launch ------------------------------------------------
extern "C" void kernel_launch(void* const* d_in, const int* in_sizes, int n_in,
                              void* d_out, int out_size)
{
    const float* t_eval = (const float*)d_in[0];
    const float* iv     = (const float*)d_in[1];
    const float* W_A    = (const float*)d_in[2];
    const float* W_B    = (const float*)d_in[3];
    const float* W1     = (const float*)d_in[4];
    const float* b1     = (const float*)d_in[5];
    const float* w2     = (const float*)d_in[6];
    const float* b2     = (const float*)d_in[7];
    const float* Tt     = (const float*)d_in[8];
    float* out = (float*)d_out;

    k_setup<<<1, 576>>>(W_A, W_B, W1, b1, w2, b2);
    k_steps<<<(NSTEP + 7) / 8, 256>>>(t_eval, Tt);
    k_scan<<<BATCH, 96>>>(iv, t_eval, Tt, out);
}